// round 9
// baseline (speedup 1.0000x reference)
#include <cuda_runtime.h>
#include <cuda_bf16.h>

// Shapes
#define Bn 8
#define Ln 128
#define Hn 768
#define Rn 24
#define Mn (Bn*Ln)   // 1024

// ---------------- scratch (__device__ globals; no allocation) ----------------
__device__ float g_pool[Bn*Hn];            // 8x768
__device__ float g_bias[2*Bn*Hn];          // [sh|oh][b][n]
__device__ float g_At[Bn*Hn*Ln];           // A transposed: [b][h][j]
__device__ float g_Ct[Bn*Hn*Ln];           // C' transposed (b_corr folded): [b][h][i]
__device__ float g_Sh[Mn*Hn];              // relu subj hidden
__device__ float g_Oh[Mn*Hn];              // relu obj hidden

// ---------------- f32x2 helpers (sm_103a packed FMA) ----------------
__device__ __forceinline__ unsigned long long pk2(float x, float y) {
    unsigned long long r;
    asm("mov.b64 %0,{%1,%2};" : "=l"(r) : "f"(x), "f"(y));
    return r;
}
__device__ __forceinline__ unsigned long long fma2(unsigned long long a,
                                                   unsigned long long b,
                                                   unsigned long long c) {
    unsigned long long d;
    asm("fma.rn.f32x2 %0,%1,%2,%3;" : "=l"(d) : "l"(a), "l"(b), "l"(c));
    return d;
}
__device__ __forceinline__ void upk2(unsigned long long v, float& x, float& y) {
    asm("mov.b64 {%0,%1},%2;" : "=f"(x), "=f"(y) : "l"(v));
}

// ---------------- 1) masked mean pool ----------------
__global__ __launch_bounds__(256) void pool_kernel(const float* __restrict__ e,
                                                   const float* __restrict__ mask) {
    int b = blockIdx.x;
    int h = blockIdx.y * 256 + threadIdx.x;   // grid.y = 3
    __shared__ float msm[Ln];
    __shared__ float sinv;
    int tid = threadIdx.x;
    if (tid < Ln) msm[tid] = mask[b*Ln + tid];
    __syncthreads();
    if (tid == 0) {
        float s = 0.f;
        for (int l = 0; l < Ln; l++) s += msm[l];
        sinv = 1.f / s;
    }
    __syncthreads();
    const float* ep = e + (size_t)b*Ln*Hn + h;
    float acc = 0.f;
    #pragma unroll 8
    for (int l = 0; l < Ln; l++) acc += ep[(size_t)l*Hn] * msm[l];
    g_pool[b*Hn + h] = acc * sinv;
}

// ---------------- 2) stage1: relu(pool@W_hr+b)@W_rj+b ----------------
__global__ __launch_bounds__(384) void stage1_kernel(const float* __restrict__ W_hr,
                                                     const float* __restrict__ b_hr,
                                                     const float* __restrict__ W_rj,
                                                     const float* __restrict__ b_rj,
                                                     float* __restrict__ out) {
    int b = blockIdx.x;
    int tid = threadIdx.x;   // 384
    __shared__ float ps[Hn];
    __shared__ float rh[Hn/2];
    for (int h = tid; h < Hn; h += 384) ps[h] = g_pool[b*Hn + h];
    __syncthreads();
    float acc = b_hr[tid];
    #pragma unroll 8
    for (int h = 0; h < Hn; h++) acc += ps[h] * W_hr[h*(Hn/2) + tid];
    rh[tid] = fmaxf(acc, 0.f);
    __syncthreads();
    if (tid < Rn) {
        float a2 = b_rj[tid];
        #pragma unroll 8
        for (int r = 0; r < Hn/2; r++) a2 += rh[r] * W_rj[r*Rn + tid];
        out[b*Rn + tid] = a2;
    }
}

// ---------------- 3) per-batch fusion biases: re@W_top + b ----------------
__global__ __launch_bounds__(256) void bias_kernel(const float* __restrict__ rel_emb,
                                                   const int* __restrict__ target,
                                                   const float* __restrict__ W_sh,
                                                   const float* __restrict__ b_sh,
                                                   const float* __restrict__ W_oh,
                                                   const float* __restrict__ b_oh) {
    int n = blockIdx.x * 256 + threadIdx.x;   // grid.x = 3
    int b = blockIdx.y;
    int z = blockIdx.z;                        // 0=sh, 1=oh
    const float* W = z ? W_oh : W_sh;          // top half rows 0..767
    const float* bias = z ? b_oh : b_sh;
    const float* re = rel_emb + (size_t)target[b]*Hn;
    float acc = 0.f;
    #pragma unroll 8
    for (int h = 0; h < Hn; h++) acc += re[h] * W[(size_t)h*Hn + n];
    g_bias[z*Bn*Hn + b*Hn + n] = acc + bias[n];
}

// ---------------- 4) unified GEMM: embed(1024x768) @ W(768x768) ----------------
// z=0: A  -> g_At transposed, no bias
// z=1: C  -> g_Ct transposed, + b_corr
// z=2: Sh -> relu(. + g_bias[0][b]) normal layout
// z=3: Oh -> relu(. + g_bias[1][b]) normal layout
#define BM 64
#define BN 64
#define BK 16
__global__ __launch_bounds__(256) void gemm_kernel(const float* __restrict__ X,
                                                   const float* __restrict__ W_corr,
                                                   const float* __restrict__ W_sh,
                                                   const float* __restrict__ W_oh,
                                                   const float* __restrict__ b_corr) {
    int z = blockIdx.z;
    const float* W;
    if (z == 0)      W = W_corr;
    else if (z == 1) W = W_corr + Hn*Hn;
    else if (z == 2) W = W_sh  + Hn*Hn;
    else             W = W_oh  + Hn*Hn;

    int m0 = blockIdx.y * BM;
    int n0 = blockIdx.x * BN;
    int tid = threadIdx.x;

    __shared__ float As[2][BK][BM];
    __shared__ float Bs[2][BK][BN];

    int arow = tid >> 2;            // 0..63
    int acol = (tid & 3) * 4;       // 0..12
    int brow = tid >> 4;            // 0..15
    int bcol = (tid & 15) * 4;      // 0..60

    const float* Aptr = X + (size_t)(m0 + arow)*Hn + acol;
    const float* Bptr = W + (size_t)brow*Hn + n0 + bcol;

    float4 av = *(const float4*)Aptr;
    float4 bv = *(const float4*)Bptr;
    As[0][acol+0][arow] = av.x;
    As[0][acol+1][arow] = av.y;
    As[0][acol+2][arow] = av.z;
    As[0][acol+3][arow] = av.w;
    *(float4*)&Bs[0][brow][bcol] = bv;
    __syncthreads();

    int tx = tid & 15, ty = tid >> 4;
    unsigned long long acc2[2][4];
    #pragma unroll
    for (int i = 0; i < 2; i++)
        #pragma unroll
        for (int j = 0; j < 4; j++) acc2[i][j] = 0ull;

    const int NT = Hn / BK;   // 48
    float4 aNxt, bNxt;
    for (int t = 0; t < NT; ++t) {
        int cur = t & 1;
        if (t + 1 < NT) {
            aNxt = *(const float4*)(Aptr + (t+1)*BK);
            bNxt = *(const float4*)(Bptr + (size_t)(t+1)*BK*Hn);
        }
        #pragma unroll
        for (int k = 0; k < BK; k++) {
            float4 af = *(const float4*)&As[cur][k][ty*4];
            float4 bf = *(const float4*)&Bs[cur][k][tx*4];
            unsigned long long a01 = pk2(af.x, af.y);
            unsigned long long a23 = pk2(af.z, af.w);
            unsigned long long bj;
            bj = pk2(bf.x, bf.x);
            acc2[0][0] = fma2(a01, bj, acc2[0][0]);
            acc2[1][0] = fma2(a23, bj, acc2[1][0]);
            bj = pk2(bf.y, bf.y);
            acc2[0][1] = fma2(a01, bj, acc2[0][1]);
            acc2[1][1] = fma2(a23, bj, acc2[1][1]);
            bj = pk2(bf.z, bf.z);
            acc2[0][2] = fma2(a01, bj, acc2[0][2]);
            acc2[1][2] = fma2(a23, bj, acc2[1][2]);
            bj = pk2(bf.w, bf.w);
            acc2[0][3] = fma2(a01, bj, acc2[0][3]);
            acc2[1][3] = fma2(a23, bj, acc2[1][3]);
        }
        if (t + 1 < NT) {
            int nxt = cur ^ 1;
            As[nxt][acol+0][arow] = aNxt.x;
            As[nxt][acol+1][arow] = aNxt.y;
            As[nxt][acol+2][arow] = aNxt.z;
            As[nxt][acol+3][arow] = aNxt.w;
            *(float4*)&Bs[nxt][brow][bcol] = bNxt;
        }
        __syncthreads();
    }

    float c[4][4];
    #pragma unroll
    for (int j = 0; j < 4; j++) {
        upk2(acc2[0][j], c[0][j], c[1][j]);
        upk2(acc2[1][j], c[2][j], c[3][j]);
    }

    if (z <= 1) {
        // transposed store: dst[b][n][l], fold b_corr for z==1
        int bb = m0 >> 7;               // batch (BM=64 never straddles batch)
        int lbase = (m0 & 127) + ty*4;  // local l, 4-aligned
        float* base = (z == 1) ? g_Ct : g_At;
        #pragma unroll
        for (int j = 0; j < 4; j++) {
            int n = n0 + tx*4 + j;
            float bias = (z == 1) ? __ldg(&b_corr[n]) : 0.f;
            float4 v = make_float4(c[0][j]+bias, c[1][j]+bias, c[2][j]+bias, c[3][j]+bias);
            *(float4*)&base[((size_t)bb*Hn + n)*Ln + lbase] = v;
        }
    } else {
        float* outp = (z == 2) ? g_Sh : g_Oh;
        const float* brow2 = g_bias + (z-2)*Bn*Hn + (m0 >> 7)*Hn + n0 + tx*4;
        float4 bias4 = *(const float4*)brow2;
        #pragma unroll
        for (int i = 0; i < 4; i++) {
            int m = m0 + ty*4 + i;
            float4 v = make_float4(fmaxf(c[i][0] + bias4.x, 0.f),
                                   fmaxf(c[i][1] + bias4.y, 0.f),
                                   fmaxf(c[i][2] + bias4.z, 0.f),
                                   fmaxf(c[i][3] + bias4.w, 0.f));
            *(float4*)&outp[(size_t)m*Hn + n0 + tx*4] = v;
        }
    }
}

// ---------------- 5) fused pred_corres ----------------
// out[b,i,j] = sum_h relu(A_t[b][h][j] + C_t[b][h][i]) * W_gc[h] + b_gc
#define CH 96
__global__ __launch_bounds__(256) void corres_kernel(const float* __restrict__ W_gc,
                                                     const float* __restrict__ b_gc,
                                                     float* __restrict__ outp) {
    int jt = blockIdx.x, it = blockIdx.y, b = blockIdx.z;
    __shared__ float Asm[CH][32];
    __shared__ float Csm[CH][32];
    __shared__ float Wsm[CH];
    int tid = threadIdx.x;
    int tx = tid & 15, ty = tid >> 4;

    const float* Abase = g_At + (size_t)b*Hn*Ln + jt*32;
    const float* Cbase = g_Ct + (size_t)b*Hn*Ln + it*32;

    float acc00 = 0.f, acc01 = 0.f, acc10 = 0.f, acc11 = 0.f;

    for (int hc = 0; hc < Hn; hc += CH) {
        __syncthreads();
        #pragma unroll
        for (int r = 0; r < 3; r++) {
            int idx = tid + r*256;           // 0..767 float4 slots
            int row = idx >> 3;
            int c4  = (idx & 7) << 2;
            *(float4*)&Asm[row][c4] = *(const float4*)&Abase[(size_t)(hc+row)*Ln + c4];
            *(float4*)&Csm[row][c4] = *(const float4*)&Cbase[(size_t)(hc+row)*Ln + c4];
        }
        if (tid < CH) Wsm[tid] = W_gc[hc + tid];
        __syncthreads();
        #pragma unroll 8
        for (int k = 0; k < CH; k++) {
            float2 a = *(const float2*)&Asm[k][tx*2];
            float2 c = *(const float2*)&Csm[k][ty*2];
            float w = Wsm[k];
            acc00 += fmaxf(a.x + c.x, 0.f) * w;
            acc01 += fmaxf(a.y + c.x, 0.f) * w;
            acc10 += fmaxf(a.x + c.y, 0.f) * w;
            acc11 += fmaxf(a.y + c.y, 0.f) * w;
        }
    }
    float bg = __ldg(b_gc);
    int i0 = it*32 + ty*2, j0 = jt*32 + tx*2;
    float* o = outp + ((size_t)b*Ln + i0)*Ln + j0;
    *(float2*)&o[0]   = make_float2(acc00 + bg, acc01 + bg);
    *(float2*)&o[Ln]  = make_float2(acc10 + bg, acc11 + bg);
}

// ---------------- 6) head projections: hidden(1024x768) @ (768x3) ----------------
__global__ __launch_bounds__(256) void head_kernel(const float* __restrict__ W_st,
                                                   const float* __restrict__ b_st,
                                                   const float* __restrict__ W_ot,
                                                   const float* __restrict__ b_ot,
                                                   float* __restrict__ out) {
    int z = blockIdx.y;  // 0=subj,1=obj
    const float* Hbuf = z ? g_Oh : g_Sh;
    const float* Wp = z ? W_ot : W_st;
    const float* bp = z ? b_ot : b_st;
    int w = threadIdx.x >> 5, lane = threadIdx.x & 31;
    int m = blockIdx.x * 8 + w;   // 0..1023
    float a0 = 0.f, a1 = 0.f, a2 = 0.f;
    const float* hr = Hbuf + (size_t)m*Hn;
    for (int h = lane; h < Hn; h += 32) {
        float v = hr[h];
        a0 += v * __ldg(&Wp[h*3 + 0]);
        a1 += v * __ldg(&Wp[h*3 + 1]);
        a2 += v * __ldg(&Wp[h*3 + 2]);
    }
    #pragma unroll
    for (int off = 16; off; off >>= 1) {
        a0 += __shfl_xor_sync(0xFFFFFFFFu, a0, off);
        a1 += __shfl_xor_sync(0xFFFFFFFFu, a1, off);
        a2 += __shfl_xor_sync(0xFFFFFFFFu, a2, off);
    }
    if (lane == 0) {
        float* o = out + (z ? (Rn*Bn + 3*Mn) : (Rn*Bn)) + m*3;
        o[0] = a0 + bp[0];
        o[1] = a1 + bp[1];
        o[2] = a2 + bp[2];
    }
}

// ---------------- launch ----------------
extern "C" void kernel_launch(void* const* d_in, const int* in_sizes, int n_in,
                              void* d_out, int out_size) {
    const float* embed   = (const float*)d_in[0];
    const float* mask    = (const float*)d_in[1];
    const int*   target  = (const int*)  d_in[2];
    const float* W_hr    = (const float*)d_in[3];
    const float* b_hr    = (const float*)d_in[4];
    const float* W_rj    = (const float*)d_in[5];
    const float* b_rj    = (const float*)d_in[6];
    const float* rel_emb = (const float*)d_in[7];
    const float* W_corr  = (const float*)d_in[8];
    const float* b_corr  = (const float*)d_in[9];
    const float* W_gc    = (const float*)d_in[10];
    const float* b_gc    = (const float*)d_in[11];
    const float* W_sh    = (const float*)d_in[12];
    const float* b_sh    = (const float*)d_in[13];
    const float* W_st    = (const float*)d_in[14];
    const float* b_st    = (const float*)d_in[15];
    const float* W_oh    = (const float*)d_in[16];
    const float* b_oh    = (const float*)d_in[17];
    const float* W_ot    = (const float*)d_in[18];
    const float* b_ot    = (const float*)d_in[19];
    float* out = (float*)d_out;

    // out layout: stage1[192] | subj[3072] | obj[3072] | pred_corres[131072]
    pool_kernel  <<<dim3(Bn, 3), 256>>>(embed, mask);
    stage1_kernel<<<Bn, 384>>>(W_hr, b_hr, W_rj, b_rj, out);
    bias_kernel  <<<dim3(3, Bn, 2), 256>>>(rel_emb, target, W_sh, b_sh, W_oh, b_oh);
    gemm_kernel  <<<dim3(Hn/BN, Mn/BM, 4), 256>>>(embed, W_corr, W_sh, W_oh, b_corr);
    corres_kernel<<<dim3(4, 4, Bn), 256>>>(W_gc, b_gc, out + Rn*Bn + 6*Mn);
    head_kernel  <<<dim3(Mn/8, 2), 256>>>(W_st, b_st, W_ot, b_ot, out);
}

// round 10
// speedup vs baseline: 1.5574x; 1.5574x over previous
#include <cuda_runtime.h>
#include <cuda_bf16.h>

// Shapes
#define Bn 8
#define Ln 128
#define Hn 768
#define Rn 24
#define Mn (Bn*Ln)   // 1024

// ---------------- scratch (__device__ globals; no allocation) ----------------
__device__ float g_pool[Bn*Hn];            // 8x768
__device__ float g_bias[2*Bn*Hn];          // [sh|oh][b][n]
__device__ float g_At[Bn*Hn*Ln];           // A transposed: [b][h][j]
__device__ float g_Ct[Bn*Hn*Ln];           // C' transposed (b_corr folded): [b][h][i]
__device__ float g_Sh[Mn*Hn];              // relu subj hidden
__device__ float g_Oh[Mn*Hn];              // relu obj hidden

// ---------------- f32x2 helpers (sm_103a packed FMA) ----------------
__device__ __forceinline__ unsigned long long pk2(float x, float y) {
    unsigned long long r;
    asm("mov.b64 %0,{%1,%2};" : "=l"(r) : "f"(x), "f"(y));
    return r;
}
__device__ __forceinline__ unsigned long long fma2(unsigned long long a,
                                                   unsigned long long b,
                                                   unsigned long long c) {
    unsigned long long d;
    asm("fma.rn.f32x2 %0,%1,%2,%3;" : "=l"(d) : "l"(a), "l"(b), "l"(c));
    return d;
}
__device__ __forceinline__ void upk2(unsigned long long v, float& x, float& y) {
    asm("mov.b64 {%0,%1},%2;" : "=f"(x), "=f"(y) : "l"(v));
}

// ---------------- 1) masked mean pool ----------------
__global__ __launch_bounds__(256) void pool_kernel(const float* __restrict__ e,
                                                   const float* __restrict__ mask) {
    int b = blockIdx.x;
    int h = blockIdx.y * 256 + threadIdx.x;   // grid.y = 3
    __shared__ float msm[Ln];
    __shared__ float sinv;
    int tid = threadIdx.x;
    if (tid < Ln) msm[tid] = mask[b*Ln + tid];
    __syncthreads();
    if (tid == 0) {
        float s = 0.f;
        for (int l = 0; l < Ln; l++) s += msm[l];
        sinv = 1.f / s;
    }
    __syncthreads();
    const float* ep = e + (size_t)b*Ln*Hn + h;
    float acc = 0.f;
    #pragma unroll 8
    for (int l = 0; l < Ln; l++) acc += ep[(size_t)l*Hn] * msm[l];
    g_pool[b*Hn + h] = acc * sinv;
}

// ---------------- 2) stage1: relu(pool@W_hr+b)@W_rj+b ----------------
__global__ __launch_bounds__(384) void stage1_kernel(const float* __restrict__ W_hr,
                                                     const float* __restrict__ b_hr,
                                                     const float* __restrict__ W_rj,
                                                     const float* __restrict__ b_rj,
                                                     float* __restrict__ out) {
    int b = blockIdx.x;
    int tid = threadIdx.x;   // 384
    __shared__ float ps[Hn];
    __shared__ float rh[Hn/2];
    for (int h = tid; h < Hn; h += 384) ps[h] = g_pool[b*Hn + h];
    __syncthreads();
    float acc = b_hr[tid];
    #pragma unroll 8
    for (int h = 0; h < Hn; h++) acc += ps[h] * W_hr[h*(Hn/2) + tid];
    rh[tid] = fmaxf(acc, 0.f);
    __syncthreads();
    if (tid < Rn) {
        float a2 = b_rj[tid];
        #pragma unroll 8
        for (int r = 0; r < Hn/2; r++) a2 += rh[r] * W_rj[r*Rn + tid];
        out[b*Rn + tid] = a2;
    }
}

// ---------------- 3) per-batch fusion biases: re@W_top + b ----------------
__global__ __launch_bounds__(256) void bias_kernel(const float* __restrict__ rel_emb,
                                                   const int* __restrict__ target,
                                                   const float* __restrict__ W_sh,
                                                   const float* __restrict__ b_sh,
                                                   const float* __restrict__ W_oh,
                                                   const float* __restrict__ b_oh) {
    int n = blockIdx.x * 256 + threadIdx.x;   // grid.x = 3
    int b = blockIdx.y;
    int z = blockIdx.z;                        // 0=sh, 1=oh
    const float* W = z ? W_oh : W_sh;          // top half rows 0..767
    const float* bias = z ? b_oh : b_sh;
    const float* re = rel_emb + (size_t)target[b]*Hn;
    float acc = 0.f;
    #pragma unroll 8
    for (int h = 0; h < Hn; h++) acc += re[h] * W[(size_t)h*Hn + n];
    g_bias[z*Bn*Hn + b*Hn + n] = acc + bias[n];
}

// ---------------- 4) unified GEMM: embed(1024x768) @ W(768x768) ----------------
// z=0: A  -> g_At transposed, no bias
// z=1: C  -> g_Ct transposed, + b_corr
// z=2: Sh -> relu(. + g_bias[0][b]) normal layout
// z=3: Oh -> relu(. + g_bias[1][b]) normal layout
#define BM 64
#define BN 64
#define BK 16
__global__ __launch_bounds__(256) void gemm_kernel(const float* __restrict__ X,
                                                   const float* __restrict__ W_corr,
                                                   const float* __restrict__ W_sh,
                                                   const float* __restrict__ W_oh,
                                                   const float* __restrict__ b_corr) {
    int z = blockIdx.z;
    const float* W;
    if (z == 0)      W = W_corr;
    else if (z == 1) W = W_corr + Hn*Hn;
    else if (z == 2) W = W_sh  + Hn*Hn;
    else             W = W_oh  + Hn*Hn;

    int m0 = blockIdx.y * BM;
    int n0 = blockIdx.x * BN;
    int tid = threadIdx.x;

    __shared__ float As[2][BK][BM];
    __shared__ float Bs[2][BK][BN];

    int arow = tid >> 2;            // 0..63
    int acol = (tid & 3) * 4;       // 0..12
    int brow = tid >> 4;            // 0..15
    int bcol = (tid & 15) * 4;      // 0..60

    const float* Aptr = X + (size_t)(m0 + arow)*Hn + acol;
    const float* Bptr = W + (size_t)brow*Hn + n0 + bcol;

    float4 av = *(const float4*)Aptr;
    float4 bv = *(const float4*)Bptr;
    As[0][acol+0][arow] = av.x;
    As[0][acol+1][arow] = av.y;
    As[0][acol+2][arow] = av.z;
    As[0][acol+3][arow] = av.w;
    *(float4*)&Bs[0][brow][bcol] = bv;
    __syncthreads();

    int tx = tid & 15, ty = tid >> 4;
    unsigned long long acc2[2][4];
    #pragma unroll
    for (int i = 0; i < 2; i++)
        #pragma unroll
        for (int j = 0; j < 4; j++) acc2[i][j] = 0ull;

    const int NT = Hn / BK;   // 48
    float4 aNxt, bNxt;
    for (int t = 0; t < NT; ++t) {
        int cur = t & 1;
        if (t + 1 < NT) {
            aNxt = *(const float4*)(Aptr + (t+1)*BK);
            bNxt = *(const float4*)(Bptr + (size_t)(t+1)*BK*Hn);
        }
        #pragma unroll
        for (int k = 0; k < BK; k++) {
            float4 af = *(const float4*)&As[cur][k][ty*4];
            float4 bf = *(const float4*)&Bs[cur][k][tx*4];
            unsigned long long a01 = pk2(af.x, af.y);
            unsigned long long a23 = pk2(af.z, af.w);
            unsigned long long bj;
            bj = pk2(bf.x, bf.x);
            acc2[0][0] = fma2(a01, bj, acc2[0][0]);
            acc2[1][0] = fma2(a23, bj, acc2[1][0]);
            bj = pk2(bf.y, bf.y);
            acc2[0][1] = fma2(a01, bj, acc2[0][1]);
            acc2[1][1] = fma2(a23, bj, acc2[1][1]);
            bj = pk2(bf.z, bf.z);
            acc2[0][2] = fma2(a01, bj, acc2[0][2]);
            acc2[1][2] = fma2(a23, bj, acc2[1][2]);
            bj = pk2(bf.w, bf.w);
            acc2[0][3] = fma2(a01, bj, acc2[0][3]);
            acc2[1][3] = fma2(a23, bj, acc2[1][3]);
        }
        if (t + 1 < NT) {
            int nxt = cur ^ 1;
            As[nxt][acol+0][arow] = aNxt.x;
            As[nxt][acol+1][arow] = aNxt.y;
            As[nxt][acol+2][arow] = aNxt.z;
            As[nxt][acol+3][arow] = aNxt.w;
            *(float4*)&Bs[nxt][brow][bcol] = bNxt;
        }
        __syncthreads();
    }

    float c[4][4];
    #pragma unroll
    for (int j = 0; j < 4; j++) {
        upk2(acc2[0][j], c[0][j], c[1][j]);
        upk2(acc2[1][j], c[2][j], c[3][j]);
    }

    if (z <= 1) {
        // transposed store: dst[b][n][l], fold b_corr for z==1
        int bb = m0 >> 7;               // batch (BM=64 never straddles batch)
        int lbase = (m0 & 127) + ty*4;  // local l, 4-aligned
        float* base = (z == 1) ? g_Ct : g_At;
        #pragma unroll
        for (int j = 0; j < 4; j++) {
            int n = n0 + tx*4 + j;
            float bias = (z == 1) ? __ldg(&b_corr[n]) : 0.f;
            float4 v = make_float4(c[0][j]+bias, c[1][j]+bias, c[2][j]+bias, c[3][j]+bias);
            *(float4*)&base[((size_t)bb*Hn + n)*Ln + lbase] = v;
        }
    } else {
        float* outp = (z == 2) ? g_Sh : g_Oh;
        const float* brow2 = g_bias + (z-2)*Bn*Hn + (m0 >> 7)*Hn + n0 + tx*4;
        float4 bias4 = *(const float4*)brow2;
        #pragma unroll
        for (int i = 0; i < 4; i++) {
            int m = m0 + ty*4 + i;
            float4 v = make_float4(fmaxf(c[i][0] + bias4.x, 0.f),
                                   fmaxf(c[i][1] + bias4.y, 0.f),
                                   fmaxf(c[i][2] + bias4.z, 0.f),
                                   fmaxf(c[i][3] + bias4.w, 0.f));
            *(float4*)&outp[(size_t)m*Hn + n0 + tx*4] = v;
        }
    }
}

// ---------------- 5) fused pred_corres ----------------
// out[b,i,j] = sum_h relu(A_t[b][h][j] + C_t[b][h][i]) * W_gc[h] + b_gc
#define CH 96
__global__ __launch_bounds__(256) void corres_kernel(const float* __restrict__ W_gc,
                                                     const float* __restrict__ b_gc,
                                                     float* __restrict__ outp) {
    int jt = blockIdx.x, it = blockIdx.y, b = blockIdx.z;
    __shared__ float Asm[CH][32];
    __shared__ float Csm[CH][32];
    __shared__ float Wsm[CH];
    int tid = threadIdx.x;
    int tx = tid & 15, ty = tid >> 4;

    const float* Abase = g_At + (size_t)b*Hn*Ln + jt*32;
    const float* Cbase = g_Ct + (size_t)b*Hn*Ln + it*32;

    float acc00 = 0.f, acc01 = 0.f, acc10 = 0.f, acc11 = 0.f;

    for (int hc = 0; hc < Hn; hc += CH) {
        __syncthreads();
        #pragma unroll
        for (int r = 0; r < 3; r++) {
            int idx = tid + r*256;           // 0..767 float4 slots
            int row = idx >> 3;
            int c4  = (idx & 7) << 2;
            *(float4*)&Asm[row][c4] = *(const float4*)&Abase[(size_t)(hc+row)*Ln + c4];
            *(float4*)&Csm[row][c4] = *(const float4*)&Cbase[(size_t)(hc+row)*Ln + c4];
        }
        if (tid < CH) Wsm[tid] = W_gc[hc + tid];
        __syncthreads();
        #pragma unroll 8
        for (int k = 0; k < CH; k++) {
            float2 a = *(const float2*)&Asm[k][tx*2];
            float2 c = *(const float2*)&Csm[k][ty*2];
            float w = Wsm[k];
            acc00 += fmaxf(a.x + c.x, 0.f) * w;
            acc01 += fmaxf(a.y + c.x, 0.f) * w;
            acc10 += fmaxf(a.x + c.y, 0.f) * w;
            acc11 += fmaxf(a.y + c.y, 0.f) * w;
        }
    }
    float bg = __ldg(b_gc);
    int i0 = it*32 + ty*2, j0 = jt*32 + tx*2;
    float* o = outp + ((size_t)b*Ln + i0)*Ln + j0;
    *(float2*)&o[0]   = make_float2(acc00 + bg, acc01 + bg);
    *(float2*)&o[Ln]  = make_float2(acc10 + bg, acc11 + bg);
}

// ---------------- 6) head projections: hidden(1024x768) @ (768x3) ----------------
__global__ __launch_bounds__(256) void head_kernel(const float* __restrict__ W_st,
                                                   const float* __restrict__ b_st,
                                                   const float* __restrict__ W_ot,
                                                   const float* __restrict__ b_ot,
                                                   float* __restrict__ out) {
    int z = blockIdx.y;  // 0=subj,1=obj
    const float* Hbuf = z ? g_Oh : g_Sh;
    const float* Wp = z ? W_ot : W_st;
    const float* bp = z ? b_ot : b_st;
    int w = threadIdx.x >> 5, lane = threadIdx.x & 31;
    int m = blockIdx.x * 8 + w;   // 0..1023
    float a0 = 0.f, a1 = 0.f, a2 = 0.f;
    const float* hr = Hbuf + (size_t)m*Hn;
    for (int h = lane; h < Hn; h += 32) {
        float v = hr[h];
        a0 += v * __ldg(&Wp[h*3 + 0]);
        a1 += v * __ldg(&Wp[h*3 + 1]);
        a2 += v * __ldg(&Wp[h*3 + 2]);
    }
    #pragma unroll
    for (int off = 16; off; off >>= 1) {
        a0 += __shfl_xor_sync(0xFFFFFFFFu, a0, off);
        a1 += __shfl_xor_sync(0xFFFFFFFFu, a1, off);
        a2 += __shfl_xor_sync(0xFFFFFFFFu, a2, off);
    }
    if (lane == 0) {
        float* o = out + (z ? (Rn*Bn + 3*Mn) : (Rn*Bn)) + m*3;
        o[0] = a0 + bp[0];
        o[1] = a1 + bp[1];
        o[2] = a2 + bp[2];
    }
}

// ---------------- launch ----------------
extern "C" void kernel_launch(void* const* d_in, const int* in_sizes, int n_in,
                              void* d_out, int out_size) {
    const float* embed   = (const float*)d_in[0];
    const float* mask    = (const float*)d_in[1];
    const int*   target  = (const int*)  d_in[2];
    const float* W_hr    = (const float*)d_in[3];
    const float* b_hr    = (const float*)d_in[4];
    const float* W_rj    = (const float*)d_in[5];
    const float* b_rj    = (const float*)d_in[6];
    const float* rel_emb = (const float*)d_in[7];
    const float* W_corr  = (const float*)d_in[8];
    const float* b_corr  = (const float*)d_in[9];
    const float* W_gc    = (const float*)d_in[10];
    const float* b_gc    = (const float*)d_in[11];
    const float* W_sh    = (const float*)d_in[12];
    const float* b_sh    = (const float*)d_in[13];
    const float* W_st    = (const float*)d_in[14];
    const float* b_st    = (const float*)d_in[15];
    const float* W_oh    = (const float*)d_in[16];
    const float* b_oh    = (const float*)d_in[17];
    const float* W_ot    = (const float*)d_in[18];
    const float* b_ot    = (const float*)d_in[19];
    float* out = (float*)d_out;

    // out layout: stage1[192] | subj[3072] | obj[3072] | pred_corres[131072]
    pool_kernel  <<<dim3(Bn, 3), 256>>>(embed, mask);
    stage1_kernel<<<Bn, 384>>>(W_hr, b_hr, W_rj, b_rj, out);
    bias_kernel  <<<dim3(3, Bn, 2), 256>>>(rel_emb, target, W_sh, b_sh, W_oh, b_oh);
    gemm_kernel  <<<dim3(Hn/BN, Mn/BM, 4), 256>>>(embed, W_corr, W_sh, W_oh, b_corr);
    corres_kernel<<<dim3(4, 4, Bn), 256>>>(W_gc, b_gc, out + Rn*Bn + 6*Mn);
    head_kernel  <<<dim3(Mn/8, 2), 256>>>(W_st, b_st, W_ot, b_ot, out);
}

// round 11
// speedup vs baseline: 1.7856x; 1.1465x over previous
#include <cuda_runtime.h>
#include <cuda_bf16.h>

// Shapes
#define Bn 8
#define Ln 128
#define Hn 768
#define Rn 24
#define Mn (Bn*Ln)   // 1024
#define RH 384       // Hn/2

// ---------------- scratch (__device__ globals; no allocation) ----------------
__device__ float g_pool[Bn*Hn];            // 8x768
__device__ float g_rh[Bn*RH];              // relu(pool@W_hr+b)
__device__ float g_bias[2*Bn*Hn];          // [sh|oh][b][n]
__device__ float g_At[Bn*Hn*Ln];           // A transposed: [b][h][j]
__device__ float g_Ct[Bn*Hn*Ln];           // C' transposed (b_corr folded): [b][h][i]
__device__ float g_Sh[Mn*Hn];              // relu subj hidden
__device__ float g_Oh[Mn*Hn];              // relu obj hidden

// ---------------- f32x2 helpers (sm_103a packed FMA) ----------------
__device__ __forceinline__ unsigned long long pk2(float x, float y) {
    unsigned long long r;
    asm("mov.b64 %0,{%1,%2};" : "=l"(r) : "f"(x), "f"(y));
    return r;
}
__device__ __forceinline__ unsigned long long fma2(unsigned long long a,
                                                   unsigned long long b,
                                                   unsigned long long c) {
    unsigned long long d;
    asm("fma.rn.f32x2 %0,%1,%2,%3;" : "=l"(d) : "l"(a), "l"(b), "l"(c));
    return d;
}
__device__ __forceinline__ void upk2(unsigned long long v, float& x, float& y) {
    asm("mov.b64 {%0,%1},%2;" : "=f"(x), "=f"(y) : "l"(v));
}

// ---------------- 1) masked mean pool ----------------
__global__ __launch_bounds__(256) void pool_kernel(const float* __restrict__ e,
                                                   const float* __restrict__ mask) {
    int b = blockIdx.x;
    int h = blockIdx.y * 256 + threadIdx.x;   // grid.y = 3
    __shared__ float msm[Ln];
    __shared__ float sinv;
    int tid = threadIdx.x;
    if (tid < Ln) msm[tid] = mask[b*Ln + tid];
    __syncthreads();
    if (tid == 0) {
        float s = 0.f;
        for (int l = 0; l < Ln; l++) s += msm[l];
        sinv = 1.f / s;
    }
    __syncthreads();
    const float* ep = e + (size_t)b*Ln*Hn + h;
    float acc = 0.f;
    #pragma unroll 8
    for (int l = 0; l < Ln; l++) acc += ep[(size_t)l*Hn] * msm[l];
    g_pool[b*Hn + h] = acc * sinv;
}

// ---------------- 2a) rel hidden: relu(pool@W_hr + b_hr) ----------------
__global__ __launch_bounds__(128) void relhid_kernel(const float* __restrict__ W_hr,
                                                     const float* __restrict__ b_hr) {
    int b = blockIdx.y;
    int r = blockIdx.x * 128 + threadIdx.x;   // grid.x = 3
    __shared__ float ps[Hn];
    for (int i = threadIdx.x; i < Hn; i += 128) ps[i] = g_pool[b*Hn + i];
    __syncthreads();
    float acc = b_hr[r];
    #pragma unroll 8
    for (int h = 0; h < Hn; h++) acc += ps[h] * W_hr[h*RH + r];
    g_rh[b*RH + r] = fmaxf(acc, 0.f);
}

// ---------------- 2b) stage1 out: rh @ W_rj + b_rj ----------------
__global__ __launch_bounds__(RH) void stage2_kernel(const float* __restrict__ W_rj,
                                                    const float* __restrict__ b_rj,
                                                    float* __restrict__ out) {
    int b = blockIdx.x;
    int tid = threadIdx.x;   // 384
    __shared__ float rs[RH];
    __shared__ float red[16][Rn];
    rs[tid] = g_rh[b*RH + tid];
    __syncthreads();
    int j = tid % Rn, part = tid / Rn;   // 16 parts x 24 j
    float acc = 0.f;
    #pragma unroll
    for (int q = 0; q < 24; q++) {
        int r = part*24 + q;
        acc += rs[r] * W_rj[r*Rn + j];
    }
    red[part][j] = acc;
    __syncthreads();
    if (tid < Rn) {
        float s = b_rj[tid];
        #pragma unroll
        for (int p = 0; p < 16; p++) s += red[p][tid];
        out[b*Rn + tid] = s;
    }
}

// ---------------- 3) per-batch fusion biases: re@W_top + b ----------------
__global__ __launch_bounds__(128) void bias_kernel(const float* __restrict__ rel_emb,
                                                   const int* __restrict__ target,
                                                   const float* __restrict__ W_sh,
                                                   const float* __restrict__ b_sh,
                                                   const float* __restrict__ W_oh,
                                                   const float* __restrict__ b_oh) {
    int n  = blockIdx.x * 128 + threadIdx.x;   // grid.x = 6
    int bp = blockIdx.y;                        // 4 batch-pairs
    int z  = blockIdx.z;                        // 0=sh, 1=oh
    const float* W = z ? W_oh : W_sh;           // top half rows 0..767
    const float* bias = z ? b_oh : b_sh;
    __shared__ float re0[Hn], re1[Hn];
    int b0 = bp*2;
    int t0 = target[b0], t1 = target[b0+1];
    for (int i = threadIdx.x; i < Hn; i += 128) {
        re0[i] = rel_emb[(size_t)t0*Hn + i];
        re1[i] = rel_emb[(size_t)t1*Hn + i];
    }
    __syncthreads();
    float a0 = 0.f, a1 = 0.f;
    #pragma unroll 8
    for (int h = 0; h < Hn; h++) {
        float w = W[(size_t)h*Hn + n];
        a0 += re0[h] * w;
        a1 += re1[h] * w;
    }
    float bs = bias[n];
    g_bias[z*Bn*Hn + b0*Hn + n]     = a0 + bs;
    g_bias[z*Bn*Hn + (b0+1)*Hn + n] = a1 + bs;
}

// ---------------- 4) unified GEMM: embed(1024x768) @ W(768x768) ----------------
// 64(M) x 128(N) block tile, BK=16, 128 threads, 8x8 microtile (f32x2 packed).
// z=0: A  -> g_At transposed; z=1: C -> g_Ct transposed + b_corr
// z=2: Sh -> relu(. + g_bias[0][b]); z=3: Oh -> relu(. + g_bias[1][b])
#define GBM 64
#define GBN 128
#define GBK 16
__global__ __launch_bounds__(128, 3) void gemm_kernel(const float* __restrict__ X,
                                                      const float* __restrict__ W_corr,
                                                      const float* __restrict__ W_sh,
                                                      const float* __restrict__ W_oh,
                                                      const float* __restrict__ b_corr) {
    int z = blockIdx.z;
    const float* W;
    if (z == 0)      W = W_corr;
    else if (z == 1) W = W_corr + Hn*Hn;
    else if (z == 2) W = W_sh  + Hn*Hn;
    else             W = W_oh  + Hn*Hn;

    int m0 = blockIdx.y * GBM;
    int n0 = blockIdx.x * GBN;
    int tid = threadIdx.x;
    int lane = tid & 31, wp = tid >> 5;

    __shared__ float As[2][GBK][GBM];    // 2 x 4KB
    __shared__ float Bs[2][GBK][GBN];    // 2 x 8KB

    // A load map: row ar (0..63), k-half ac (0/1) -> k offsets ac*8, ac*8+4
    int ar = tid & 63, ac = tid >> 6;
    const float* Ap = X + (size_t)(m0 + ar)*Hn + ac*8;
    // B load map: warp wp rows k = wp*4 + t, lane = n-chunk
    const float* Bp = W + (size_t)(wp*4)*Hn + n0 + lane*4;

    float4 a0 = *(const float4*)Ap;
    float4 a1 = *(const float4*)(Ap + 4);
    float4 bv0 = *(const float4*)(Bp);
    float4 bv1 = *(const float4*)(Bp + Hn);
    float4 bv2 = *(const float4*)(Bp + 2*Hn);
    float4 bv3 = *(const float4*)(Bp + 3*Hn);

    As[0][ac*8+0][ar] = a0.x; As[0][ac*8+1][ar] = a0.y;
    As[0][ac*8+2][ar] = a0.z; As[0][ac*8+3][ar] = a0.w;
    As[0][ac*8+4][ar] = a1.x; As[0][ac*8+5][ar] = a1.y;
    As[0][ac*8+6][ar] = a1.z; As[0][ac*8+7][ar] = a1.w;
    *(float4*)&Bs[0][wp*4+0][lane*4] = bv0;
    *(float4*)&Bs[0][wp*4+1][lane*4] = bv1;
    *(float4*)&Bs[0][wp*4+2][lane*4] = bv2;
    *(float4*)&Bs[0][wp*4+3][lane*4] = bv3;
    __syncthreads();

    int tx = tid & 15, ty = tid >> 4;   // 16 x 8 thread grid -> 128N x 64M

    unsigned long long acc2[4][8];
    #pragma unroll
    for (int p = 0; p < 4; p++)
        #pragma unroll
        for (int j = 0; j < 8; j++) acc2[p][j] = 0ull;

    const int NT = Hn / GBK;   // 48
    for (int t = 0; t < NT; ++t) {
        int cur = t & 1;
        if (t + 1 < NT) {
            const float* ap2 = Ap + (t+1)*GBK;
            a0 = *(const float4*)ap2;
            a1 = *(const float4*)(ap2 + 4);
            const float* bp2 = Bp + (size_t)(t+1)*GBK*Hn;
            bv0 = *(const float4*)(bp2);
            bv1 = *(const float4*)(bp2 + Hn);
            bv2 = *(const float4*)(bp2 + 2*Hn);
            bv3 = *(const float4*)(bp2 + 3*Hn);
        }
        #pragma unroll
        for (int k = 0; k < GBK; k++) {
            float4 af0 = *(const float4*)&As[cur][k][ty*8];
            float4 af1 = *(const float4*)&As[cur][k][ty*8 + 4];
            float4 bf0 = *(const float4*)&Bs[cur][k][tx*8];
            float4 bf1 = *(const float4*)&Bs[cur][k][tx*8 + 4];
            unsigned long long a01 = pk2(af0.x, af0.y);
            unsigned long long a23 = pk2(af0.z, af0.w);
            unsigned long long a45 = pk2(af1.x, af1.y);
            unsigned long long a67 = pk2(af1.z, af1.w);
            float bb[8] = {bf0.x, bf0.y, bf0.z, bf0.w, bf1.x, bf1.y, bf1.z, bf1.w};
            #pragma unroll
            for (int j = 0; j < 8; j++) {
                unsigned long long bj = pk2(bb[j], bb[j]);
                acc2[0][j] = fma2(a01, bj, acc2[0][j]);
                acc2[1][j] = fma2(a23, bj, acc2[1][j]);
                acc2[2][j] = fma2(a45, bj, acc2[2][j]);
                acc2[3][j] = fma2(a67, bj, acc2[3][j]);
            }
        }
        if (t + 1 < NT) {
            int nxt = cur ^ 1;
            As[nxt][ac*8+0][ar] = a0.x; As[nxt][ac*8+1][ar] = a0.y;
            As[nxt][ac*8+2][ar] = a0.z; As[nxt][ac*8+3][ar] = a0.w;
            As[nxt][ac*8+4][ar] = a1.x; As[nxt][ac*8+5][ar] = a1.y;
            As[nxt][ac*8+6][ar] = a1.z; As[nxt][ac*8+7][ar] = a1.w;
            *(float4*)&Bs[nxt][wp*4+0][lane*4] = bv0;
            *(float4*)&Bs[nxt][wp*4+1][lane*4] = bv1;
            *(float4*)&Bs[nxt][wp*4+2][lane*4] = bv2;
            *(float4*)&Bs[nxt][wp*4+3][lane*4] = bv3;
        }
        __syncthreads();
    }

    float cr[8][8];
    #pragma unroll
    for (int j = 0; j < 8; j++) {
        upk2(acc2[0][j], cr[0][j], cr[1][j]);
        upk2(acc2[1][j], cr[2][j], cr[3][j]);
        upk2(acc2[2][j], cr[4][j], cr[5][j]);
        upk2(acc2[3][j], cr[6][j], cr[7][j]);
    }

    if (z <= 1) {
        // transposed store: dst[b][n][l], fold b_corr for z==1
        int bb2 = m0 >> 7;                // BM=64 never straddles batch
        int l0 = (m0 & 127) + ty*8;
        float* base = (z == 1) ? g_Ct : g_At;
        #pragma unroll
        for (int j = 0; j < 8; j++) {
            int n = n0 + tx*8 + j;
            float bias = (z == 1) ? __ldg(&b_corr[n]) : 0.f;
            float4 v0 = make_float4(cr[0][j]+bias, cr[1][j]+bias, cr[2][j]+bias, cr[3][j]+bias);
            float4 v1 = make_float4(cr[4][j]+bias, cr[5][j]+bias, cr[6][j]+bias, cr[7][j]+bias);
            float* d = base + ((size_t)bb2*Hn + n)*Ln + l0;
            *(float4*)d = v0;
            *(float4*)(d + 4) = v1;
        }
    } else {
        float* outp = (z == 2) ? g_Sh : g_Oh;
        const float* bp = g_bias + (z-2)*Bn*Hn + (m0 >> 7)*Hn + n0 + tx*8;
        float4 b4a = *(const float4*)bp;
        float4 b4b = *(const float4*)(bp + 4);
        #pragma unroll
        for (int i = 0; i < 8; i++) {
            int m = m0 + ty*8 + i;
            float4 v0 = make_float4(fmaxf(cr[i][0] + b4a.x, 0.f),
                                    fmaxf(cr[i][1] + b4a.y, 0.f),
                                    fmaxf(cr[i][2] + b4a.z, 0.f),
                                    fmaxf(cr[i][3] + b4a.w, 0.f));
            float4 v1 = make_float4(fmaxf(cr[i][4] + b4b.x, 0.f),
                                    fmaxf(cr[i][5] + b4b.y, 0.f),
                                    fmaxf(cr[i][6] + b4b.z, 0.f),
                                    fmaxf(cr[i][7] + b4b.w, 0.f));
            float* d = outp + (size_t)m*Hn + n0 + tx*8;
            *(float4*)d = v0;
            *(float4*)(d + 4) = v1;
        }
    }
}

// ---------------- 5) fused pred_corres ----------------
// out[b,i,j] = sum_h relu(A_t[b][h][j] + C_t[b][h][i]) * W_gc[h] + b_gc
#define CH 96
__global__ __launch_bounds__(256) void corres_kernel(const float* __restrict__ W_gc,
                                                     const float* __restrict__ b_gc,
                                                     float* __restrict__ outp) {
    int jt = blockIdx.x, it = blockIdx.y, b = blockIdx.z;
    __shared__ float Asm[CH][32];
    __shared__ float Csm[CH][32];
    __shared__ float Wsm[CH];
    int tid = threadIdx.x;
    int tx = tid & 15, ty = tid >> 4;

    const float* Abase = g_At + (size_t)b*Hn*Ln + jt*32;
    const float* Cbase = g_Ct + (size_t)b*Hn*Ln + it*32;

    float acc00 = 0.f, acc01 = 0.f, acc10 = 0.f, acc11 = 0.f;

    for (int hc = 0; hc < Hn; hc += CH) {
        __syncthreads();
        #pragma unroll
        for (int r = 0; r < 3; r++) {
            int idx = tid + r*256;           // 0..767 float4 slots
            int row = idx >> 3;
            int c4  = (idx & 7) << 2;
            *(float4*)&Asm[row][c4] = *(const float4*)&Abase[(size_t)(hc+row)*Ln + c4];
            *(float4*)&Csm[row][c4] = *(const float4*)&Cbase[(size_t)(hc+row)*Ln + c4];
        }
        if (tid < CH) Wsm[tid] = W_gc[hc + tid];
        __syncthreads();
        #pragma unroll 8
        for (int k = 0; k < CH; k++) {
            float2 a = *(const float2*)&Asm[k][tx*2];
            float2 c = *(const float2*)&Csm[k][ty*2];
            float w = Wsm[k];
            acc00 += fmaxf(a.x + c.x, 0.f) * w;
            acc01 += fmaxf(a.y + c.x, 0.f) * w;
            acc10 += fmaxf(a.x + c.y, 0.f) * w;
            acc11 += fmaxf(a.y + c.y, 0.f) * w;
        }
    }
    float bg = __ldg(b_gc);
    int i0 = it*32 + ty*2, j0 = jt*32 + tx*2;
    float* o = outp + ((size_t)b*Ln + i0)*Ln + j0;
    *(float2*)&o[0]   = make_float2(acc00 + bg, acc01 + bg);
    *(float2*)&o[Ln]  = make_float2(acc10 + bg, acc11 + bg);
}

// ---------------- 6) head projections: hidden(1024x768) @ (768x3) ----------------
__global__ __launch_bounds__(256) void head_kernel(const float* __restrict__ W_st,
                                                   const float* __restrict__ b_st,
                                                   const float* __restrict__ W_ot,
                                                   const float* __restrict__ b_ot,
                                                   float* __restrict__ out) {
    int z = blockIdx.y;  // 0=subj,1=obj
    const float* Hbuf = z ? g_Oh : g_Sh;
    const float* Wp = z ? W_ot : W_st;
    const float* bp = z ? b_ot : b_st;
    int w = threadIdx.x >> 5, lane = threadIdx.x & 31;
    int m = blockIdx.x * 8 + w;   // 0..1023
    float a0 = 0.f, a1 = 0.f, a2 = 0.f;
    const float* hr = Hbuf + (size_t)m*Hn;
    for (int h = lane; h < Hn; h += 32) {
        float v = hr[h];
        a0 += v * __ldg(&Wp[h*3 + 0]);
        a1 += v * __ldg(&Wp[h*3 + 1]);
        a2 += v * __ldg(&Wp[h*3 + 2]);
    }
    #pragma unroll
    for (int off = 16; off; off >>= 1) {
        a0 += __shfl_xor_sync(0xFFFFFFFFu, a0, off);
        a1 += __shfl_xor_sync(0xFFFFFFFFu, a1, off);
        a2 += __shfl_xor_sync(0xFFFFFFFFu, a2, off);
    }
    if (lane == 0) {
        float* o = out + (z ? (Rn*Bn + 3*Mn) : (Rn*Bn)) + m*3;
        o[0] = a0 + bp[0];
        o[1] = a1 + bp[1];
        o[2] = a2 + bp[2];
    }
}

// ---------------- launch ----------------
extern "C" void kernel_launch(void* const* d_in, const int* in_sizes, int n_in,
                              void* d_out, int out_size) {
    const float* embed   = (const float*)d_in[0];
    const float* mask    = (const float*)d_in[1];
    const int*   target  = (const int*)  d_in[2];
    const float* W_hr    = (const float*)d_in[3];
    const float* b_hr    = (const float*)d_in[4];
    const float* W_rj    = (const float*)d_in[5];
    const float* b_rj    = (const float*)d_in[6];
    const float* rel_emb = (const float*)d_in[7];
    const float* W_corr  = (const float*)d_in[8];
    const float* b_corr  = (const float*)d_in[9];
    const float* W_gc    = (const float*)d_in[10];
    const float* b_gc    = (const float*)d_in[11];
    const float* W_sh    = (const float*)d_in[12];
    const float* b_sh    = (const float*)d_in[13];
    const float* W_st    = (const float*)d_in[14];
    const float* b_st    = (const float*)d_in[15];
    const float* W_oh    = (const float*)d_in[16];
    const float* b_oh    = (const float*)d_in[17];
    const float* W_ot    = (const float*)d_in[18];
    const float* b_ot    = (const float*)d_in[19];
    float* out = (float*)d_out;

    // out layout: stage1[192] | subj[3072] | obj[3072] | pred_corres[131072]
    pool_kernel  <<<dim3(Bn, 3), 256>>>(embed, mask);
    relhid_kernel<<<dim3(3, Bn), 128>>>(W_hr, b_hr);
    stage2_kernel<<<Bn, RH>>>(W_rj, b_rj, out);
    bias_kernel  <<<dim3(6, 4, 2), 128>>>(rel_emb, target, W_sh, b_sh, W_oh, b_oh);
    gemm_kernel  <<<dim3(Hn/GBN, Mn/GBM, 4), 128>>>(embed, W_corr, W_sh, W_oh, b_corr);
    corres_kernel<<<dim3(4, 4, Bn), 256>>>(W_gc, b_gc, out + Rn*Bn + 6*Mn);
    head_kernel  <<<dim3(Mn/8, 2), 256>>>(W_st, b_st, W_ot, b_ot, out);
}

// round 12
// speedup vs baseline: 1.8014x; 1.0089x over previous
#include <cuda_runtime.h>
#include <cuda_bf16.h>

// Shapes
#define Bn 8
#define Ln 128
#define Hn 768
#define Rn 24
#define Mn (Bn*Ln)   // 1024
#define RH 384       // Hn/2

// ---------------- scratch (__device__ globals; no allocation) ----------------
__device__ float g_pool[Bn*Hn];            // 8x768
__device__ float g_rh[Bn*RH];              // relu(pool@W_hr+b)
__device__ float g_bias[2*Bn*Hn];          // [sh|oh][b][n]
__device__ float g_At[Bn*Hn*Ln];           // A transposed: [b][h][j]
__device__ float g_Ct[Bn*Hn*Ln];           // C' transposed (b_corr folded): [b][h][i]
__device__ float g_Sh[Mn*Hn];              // relu subj hidden
__device__ float g_Oh[Mn*Hn];              // relu obj hidden

// ---------------- f32x2 helpers (sm_103a packed FMA) ----------------
__device__ __forceinline__ unsigned long long pk2(float x, float y) {
    unsigned long long r;
    asm("mov.b64 %0,{%1,%2};" : "=l"(r) : "f"(x), "f"(y));
    return r;
}
__device__ __forceinline__ unsigned long long fma2(unsigned long long a,
                                                   unsigned long long b,
                                                   unsigned long long c) {
    unsigned long long d;
    asm("fma.rn.f32x2 %0,%1,%2,%3;" : "=l"(d) : "l"(a), "l"(b), "l"(c));
    return d;
}
__device__ __forceinline__ void upk2(unsigned long long v, float& x, float& y) {
    asm("mov.b64 {%0,%1},%2;" : "=f"(x), "=f"(y) : "l"(v));
}

// ---------------- 1) masked mean pool ----------------
__global__ __launch_bounds__(256) void pool_kernel(const float* __restrict__ e,
                                                   const float* __restrict__ mask) {
    int b = blockIdx.x;
    int h = blockIdx.y * 256 + threadIdx.x;   // grid.y = 3
    __shared__ float msm[Ln];
    __shared__ float sinv;
    int tid = threadIdx.x;
    if (tid < Ln) msm[tid] = mask[b*Ln + tid];
    __syncthreads();
    if (tid == 0) {
        float s = 0.f;
        for (int l = 0; l < Ln; l++) s += msm[l];
        sinv = 1.f / s;
    }
    __syncthreads();
    const float* ep = e + (size_t)b*Ln*Hn + h;
    float acc = 0.f;
    #pragma unroll 8
    for (int l = 0; l < Ln; l++) acc += ep[(size_t)l*Hn] * msm[l];
    g_pool[b*Hn + h] = acc * sinv;
}

// ---------------- 2a) rel hidden: relu(pool@W_hr + b_hr) ----------------
__global__ __launch_bounds__(128) void relhid_kernel(const float* __restrict__ W_hr,
                                                     const float* __restrict__ b_hr) {
    int b = blockIdx.y;
    int r = blockIdx.x * 128 + threadIdx.x;   // grid.x = 3
    __shared__ float ps[Hn];
    for (int i = threadIdx.x; i < Hn; i += 128) ps[i] = g_pool[b*Hn + i];
    __syncthreads();
    float acc = b_hr[r];
    #pragma unroll 8
    for (int h = 0; h < Hn; h++) acc += ps[h] * W_hr[h*RH + r];
    g_rh[b*RH + r] = fmaxf(acc, 0.f);
}

// ---------------- 2b) stage1 out: rh @ W_rj + b_rj ----------------
__global__ __launch_bounds__(RH) void stage2_kernel(const float* __restrict__ W_rj,
                                                    const float* __restrict__ b_rj,
                                                    float* __restrict__ out) {
    int b = blockIdx.x;
    int tid = threadIdx.x;   // 384
    __shared__ float rs[RH];
    __shared__ float red[16][Rn];
    rs[tid] = g_rh[b*RH + tid];
    __syncthreads();
    int j = tid % Rn, part = tid / Rn;   // 16 parts x 24 j
    float acc = 0.f;
    #pragma unroll
    for (int q = 0; q < 24; q++) {
        int r = part*24 + q;
        acc += rs[r] * W_rj[r*Rn + j];
    }
    red[part][j] = acc;
    __syncthreads();
    if (tid < Rn) {
        float s = b_rj[tid];
        #pragma unroll
        for (int p = 0; p < 16; p++) s += red[p][tid];
        out[b*Rn + tid] = s;
    }
}

// ---------------- 3) per-batch fusion biases: re@W_top + b ----------------
__global__ __launch_bounds__(128) void bias_kernel(const float* __restrict__ rel_emb,
                                                   const int* __restrict__ target,
                                                   const float* __restrict__ W_sh,
                                                   const float* __restrict__ b_sh,
                                                   const float* __restrict__ W_oh,
                                                   const float* __restrict__ b_oh) {
    int n  = blockIdx.x * 128 + threadIdx.x;   // grid.x = 6
    int bp = blockIdx.y;                        // 4 batch-pairs
    int z  = blockIdx.z;                        // 0=sh, 1=oh
    const float* W = z ? W_oh : W_sh;           // top half rows 0..767
    const float* bias = z ? b_oh : b_sh;
    __shared__ float re0[Hn], re1[Hn];
    int b0 = bp*2;
    int t0 = target[b0], t1 = target[b0+1];
    for (int i = threadIdx.x; i < Hn; i += 128) {
        re0[i] = rel_emb[(size_t)t0*Hn + i];
        re1[i] = rel_emb[(size_t)t1*Hn + i];
    }
    __syncthreads();
    float a0 = 0.f, a1 = 0.f;
    #pragma unroll 8
    for (int h = 0; h < Hn; h++) {
        float w = W[(size_t)h*Hn + n];
        a0 += re0[h] * w;
        a1 += re1[h] * w;
    }
    float bs = bias[n];
    g_bias[z*Bn*Hn + b0*Hn + n]     = a0 + bs;
    g_bias[z*Bn*Hn + (b0+1)*Hn + n] = a1 + bs;
}

// ---------------- 4) unified GEMM: embed(1024x768) @ W(768x768) ----------------
// 64(M) x 128(N) block tile, BK=16, 128 threads, 8x8 microtile (f32x2 packed).
// z=0: A  -> g_At transposed; z=1: C -> g_Ct transposed + b_corr
// z=2: Sh -> relu(. + g_bias[0][b]); z=3: Oh -> relu(. + g_bias[1][b])
#define GBM 64
#define GBN 128
#define GBK 16
__global__ __launch_bounds__(128, 3) void gemm_kernel(const float* __restrict__ X,
                                                      const float* __restrict__ W_corr,
                                                      const float* __restrict__ W_sh,
                                                      const float* __restrict__ W_oh,
                                                      const float* __restrict__ b_corr) {
    int z = blockIdx.z;
    const float* W;
    if (z == 0)      W = W_corr;
    else if (z == 1) W = W_corr + Hn*Hn;
    else if (z == 2) W = W_sh  + Hn*Hn;
    else             W = W_oh  + Hn*Hn;

    int m0 = blockIdx.y * GBM;
    int n0 = blockIdx.x * GBN;
    int tid = threadIdx.x;
    int lane = tid & 31, wp = tid >> 5;

    __shared__ float As[2][GBK][GBM];    // 2 x 4KB
    __shared__ float Bs[2][GBK][GBN];    // 2 x 8KB

    // A load map: row ar (0..63), k-half ac (0/1) -> k offsets ac*8, ac*8+4
    int ar = tid & 63, ac = tid >> 6;
    const float* Ap = X + (size_t)(m0 + ar)*Hn + ac*8;
    // B load map: warp wp rows k = wp*4 + t, lane = n-chunk
    const float* Bp = W + (size_t)(wp*4)*Hn + n0 + lane*4;

    float4 a0 = *(const float4*)Ap;
    float4 a1 = *(const float4*)(Ap + 4);
    float4 bv0 = *(const float4*)(Bp);
    float4 bv1 = *(const float4*)(Bp + Hn);
    float4 bv2 = *(const float4*)(Bp + 2*Hn);
    float4 bv3 = *(const float4*)(Bp + 3*Hn);

    As[0][ac*8+0][ar] = a0.x; As[0][ac*8+1][ar] = a0.y;
    As[0][ac*8+2][ar] = a0.z; As[0][ac*8+3][ar] = a0.w;
    As[0][ac*8+4][ar] = a1.x; As[0][ac*8+5][ar] = a1.y;
    As[0][ac*8+6][ar] = a1.z; As[0][ac*8+7][ar] = a1.w;
    *(float4*)&Bs[0][wp*4+0][lane*4] = bv0;
    *(float4*)&Bs[0][wp*4+1][lane*4] = bv1;
    *(float4*)&Bs[0][wp*4+2][lane*4] = bv2;
    *(float4*)&Bs[0][wp*4+3][lane*4] = bv3;
    __syncthreads();

    int tx = tid & 15, ty = tid >> 4;   // 16 x 8 thread grid -> 128N x 64M

    unsigned long long acc2[4][8];
    #pragma unroll
    for (int p = 0; p < 4; p++)
        #pragma unroll
        for (int j = 0; j < 8; j++) acc2[p][j] = 0ull;

    const int NT = Hn / GBK;   // 48
    for (int t = 0; t < NT; ++t) {
        int cur = t & 1;
        if (t + 1 < NT) {
            const float* ap2 = Ap + (t+1)*GBK;
            a0 = *(const float4*)ap2;
            a1 = *(const float4*)(ap2 + 4);
            const float* bp2 = Bp + (size_t)(t+1)*GBK*Hn;
            bv0 = *(const float4*)(bp2);
            bv1 = *(const float4*)(bp2 + Hn);
            bv2 = *(const float4*)(bp2 + 2*Hn);
            bv3 = *(const float4*)(bp2 + 3*Hn);
        }
        #pragma unroll
        for (int k = 0; k < GBK; k++) {
            float4 af0 = *(const float4*)&As[cur][k][ty*8];
            float4 af1 = *(const float4*)&As[cur][k][ty*8 + 4];
            float4 bf0 = *(const float4*)&Bs[cur][k][tx*8];
            float4 bf1 = *(const float4*)&Bs[cur][k][tx*8 + 4];
            unsigned long long a01 = pk2(af0.x, af0.y);
            unsigned long long a23 = pk2(af0.z, af0.w);
            unsigned long long a45 = pk2(af1.x, af1.y);
            unsigned long long a67 = pk2(af1.z, af1.w);
            float bb[8] = {bf0.x, bf0.y, bf0.z, bf0.w, bf1.x, bf1.y, bf1.z, bf1.w};
            #pragma unroll
            for (int j = 0; j < 8; j++) {
                unsigned long long bj = pk2(bb[j], bb[j]);
                acc2[0][j] = fma2(a01, bj, acc2[0][j]);
                acc2[1][j] = fma2(a23, bj, acc2[1][j]);
                acc2[2][j] = fma2(a45, bj, acc2[2][j]);
                acc2[3][j] = fma2(a67, bj, acc2[3][j]);
            }
        }
        if (t + 1 < NT) {
            int nxt = cur ^ 1;
            As[nxt][ac*8+0][ar] = a0.x; As[nxt][ac*8+1][ar] = a0.y;
            As[nxt][ac*8+2][ar] = a0.z; As[nxt][ac*8+3][ar] = a0.w;
            As[nxt][ac*8+4][ar] = a1.x; As[nxt][ac*8+5][ar] = a1.y;
            As[nxt][ac*8+6][ar] = a1.z; As[nxt][ac*8+7][ar] = a1.w;
            *(float4*)&Bs[nxt][wp*4+0][lane*4] = bv0;
            *(float4*)&Bs[nxt][wp*4+1][lane*4] = bv1;
            *(float4*)&Bs[nxt][wp*4+2][lane*4] = bv2;
            *(float4*)&Bs[nxt][wp*4+3][lane*4] = bv3;
        }
        __syncthreads();
    }

    float cr[8][8];
    #pragma unroll
    for (int j = 0; j < 8; j++) {
        upk2(acc2[0][j], cr[0][j], cr[1][j]);
        upk2(acc2[1][j], cr[2][j], cr[3][j]);
        upk2(acc2[2][j], cr[4][j], cr[5][j]);
        upk2(acc2[3][j], cr[6][j], cr[7][j]);
    }

    if (z <= 1) {
        // transposed store: dst[b][n][l], fold b_corr for z==1
        int bb2 = m0 >> 7;                // BM=64 never straddles batch
        int l0 = (m0 & 127) + ty*8;
        float* base = (z == 1) ? g_Ct : g_At;
        #pragma unroll
        for (int j = 0; j < 8; j++) {
            int n = n0 + tx*8 + j;
            float bias = (z == 1) ? __ldg(&b_corr[n]) : 0.f;
            float4 v0 = make_float4(cr[0][j]+bias, cr[1][j]+bias, cr[2][j]+bias, cr[3][j]+bias);
            float4 v1 = make_float4(cr[4][j]+bias, cr[5][j]+bias, cr[6][j]+bias, cr[7][j]+bias);
            float* d = base + ((size_t)bb2*Hn + n)*Ln + l0;
            *(float4*)d = v0;
            *(float4*)(d + 4) = v1;
        }
    } else {
        float* outp = (z == 2) ? g_Sh : g_Oh;
        const float* bp = g_bias + (z-2)*Bn*Hn + (m0 >> 7)*Hn + n0 + tx*8;
        float4 b4a = *(const float4*)bp;
        float4 b4b = *(const float4*)(bp + 4);
        #pragma unroll
        for (int i = 0; i < 8; i++) {
            int m = m0 + ty*8 + i;
            float4 v0 = make_float4(fmaxf(cr[i][0] + b4a.x, 0.f),
                                    fmaxf(cr[i][1] + b4a.y, 0.f),
                                    fmaxf(cr[i][2] + b4a.z, 0.f),
                                    fmaxf(cr[i][3] + b4a.w, 0.f));
            float4 v1 = make_float4(fmaxf(cr[i][4] + b4b.x, 0.f),
                                    fmaxf(cr[i][5] + b4b.y, 0.f),
                                    fmaxf(cr[i][6] + b4b.z, 0.f),
                                    fmaxf(cr[i][7] + b4b.w, 0.f));
            float* d = outp + (size_t)m*Hn + n0 + tx*8;
            *(float4*)d = v0;
            *(float4*)(d + 4) = v1;
        }
    }
}

// ---------------- 5) fused pred_corres ----------------
// out[b,i,j] = sum_h relu(A_t[b][h][j] + C_t[b][h][i]) * W_gc[h] + b_gc
#define CH 96
__global__ __launch_bounds__(256) void corres_kernel(const float* __restrict__ W_gc,
                                                     const float* __restrict__ b_gc,
                                                     float* __restrict__ outp) {
    int jt = blockIdx.x, it = blockIdx.y, b = blockIdx.z;
    __shared__ float Asm[CH][32];
    __shared__ float Csm[CH][32];
    __shared__ float Wsm[CH];
    int tid = threadIdx.x;
    int tx = tid & 15, ty = tid >> 4;

    const float* Abase = g_At + (size_t)b*Hn*Ln + jt*32;
    const float* Cbase = g_Ct + (size_t)b*Hn*Ln + it*32;

    float acc00 = 0.f, acc01 = 0.f, acc10 = 0.f, acc11 = 0.f;

    for (int hc = 0; hc < Hn; hc += CH) {
        __syncthreads();
        #pragma unroll
        for (int r = 0; r < 3; r++) {
            int idx = tid + r*256;           // 0..767 float4 slots
            int row = idx >> 3;
            int c4  = (idx & 7) << 2;
            *(float4*)&Asm[row][c4] = *(const float4*)&Abase[(size_t)(hc+row)*Ln + c4];
            *(float4*)&Csm[row][c4] = *(const float4*)&Cbase[(size_t)(hc+row)*Ln + c4];
        }
        if (tid < CH) Wsm[tid] = W_gc[hc + tid];
        __syncthreads();
        #pragma unroll 8
        for (int k = 0; k < CH; k++) {
            float2 a = *(const float2*)&Asm[k][tx*2];
            float2 c = *(const float2*)&Csm[k][ty*2];
            float w = Wsm[k];
            acc00 += fmaxf(a.x + c.x, 0.f) * w;
            acc01 += fmaxf(a.y + c.x, 0.f) * w;
            acc10 += fmaxf(a.x + c.y, 0.f) * w;
            acc11 += fmaxf(a.y + c.y, 0.f) * w;
        }
    }
    float bg = __ldg(b_gc);
    int i0 = it*32 + ty*2, j0 = jt*32 + tx*2;
    float* o = outp + ((size_t)b*Ln + i0)*Ln + j0;
    *(float2*)&o[0]   = make_float2(acc00 + bg, acc01 + bg);
    *(float2*)&o[Ln]  = make_float2(acc10 + bg, acc11 + bg);
}

// ---------------- 6) head projections: hidden(1024x768) @ (768x3) ----------------
__global__ __launch_bounds__(256) void head_kernel(const float* __restrict__ W_st,
                                                   const float* __restrict__ b_st,
                                                   const float* __restrict__ W_ot,
                                                   const float* __restrict__ b_ot,
                                                   float* __restrict__ out) {
    int z = blockIdx.y;  // 0=subj,1=obj
    const float* Hbuf = z ? g_Oh : g_Sh;
    const float* Wp = z ? W_ot : W_st;
    const float* bp = z ? b_ot : b_st;
    int w = threadIdx.x >> 5, lane = threadIdx.x & 31;
    int m = blockIdx.x * 8 + w;   // 0..1023
    float a0 = 0.f, a1 = 0.f, a2 = 0.f;
    const float* hr = Hbuf + (size_t)m*Hn;
    for (int h = lane; h < Hn; h += 32) {
        float v = hr[h];
        a0 += v * __ldg(&Wp[h*3 + 0]);
        a1 += v * __ldg(&Wp[h*3 + 1]);
        a2 += v * __ldg(&Wp[h*3 + 2]);
    }
    #pragma unroll
    for (int off = 16; off; off >>= 1) {
        a0 += __shfl_xor_sync(0xFFFFFFFFu, a0, off);
        a1 += __shfl_xor_sync(0xFFFFFFFFu, a1, off);
        a2 += __shfl_xor_sync(0xFFFFFFFFu, a2, off);
    }
    if (lane == 0) {
        float* o = out + (z ? (Rn*Bn + 3*Mn) : (Rn*Bn)) + m*3;
        o[0] = a0 + bp[0];
        o[1] = a1 + bp[1];
        o[2] = a2 + bp[2];
    }
}

// ---------------- launch ----------------
extern "C" void kernel_launch(void* const* d_in, const int* in_sizes, int n_in,
                              void* d_out, int out_size) {
    const float* embed   = (const float*)d_in[0];
    const float* mask    = (const float*)d_in[1];
    const int*   target  = (const int*)  d_in[2];
    const float* W_hr    = (const float*)d_in[3];
    const float* b_hr    = (const float*)d_in[4];
    const float* W_rj    = (const float*)d_in[5];
    const float* b_rj    = (const float*)d_in[6];
    const float* rel_emb = (const float*)d_in[7];
    const float* W_corr  = (const float*)d_in[8];
    const float* b_corr  = (const float*)d_in[9];
    const float* W_gc    = (const float*)d_in[10];
    const float* b_gc    = (const float*)d_in[11];
    const float* W_sh    = (const float*)d_in[12];
    const float* b_sh    = (const float*)d_in[13];
    const float* W_st    = (const float*)d_in[14];
    const float* b_st    = (const float*)d_in[15];
    const float* W_oh    = (const float*)d_in[16];
    const float* b_oh    = (const float*)d_in[17];
    const float* W_ot    = (const float*)d_in[18];
    const float* b_ot    = (const float*)d_in[19];
    float* out = (float*)d_out;

    // out layout: stage1[192] | subj[3072] | obj[3072] | pred_corres[131072]
    pool_kernel  <<<dim3(Bn, 3), 256>>>(embed, mask);
    relhid_kernel<<<dim3(3, Bn), 128>>>(W_hr, b_hr);
    stage2_kernel<<<Bn, RH>>>(W_rj, b_rj, out);
    bias_kernel  <<<dim3(6, 4, 2), 128>>>(rel_emb, target, W_sh, b_sh, W_oh, b_oh);
    gemm_kernel  <<<dim3(Hn/GBN, Mn/GBM, 4), 128>>>(embed, W_corr, W_sh, W_oh, b_corr);
    corres_kernel<<<dim3(4, 4, Bn), 256>>>(W_gc, b_gc, out + Rn*Bn + 6*Mn);
    head_kernel  <<<dim3(Mn/8, 2), 256>>>(W_st, b_st, W_ot, b_ot, out);
}

// round 13
// speedup vs baseline: 2.0931x; 1.1620x over previous
#include <cuda_runtime.h>
#include <cuda_bf16.h>

// Shapes
#define Bn 8
#define Ln 128
#define Hn 768
#define Rn 24
#define Mn (Bn*Ln)   // 1024
#define RH 384       // Hn/2

// ---------------- scratch (__device__ globals; no allocation) ----------------
__device__ float g_pool[Bn*Hn];            // 8x768
__device__ float g_rhPart[4][Bn][RH];      // split-K partials for rel hidden
__device__ float g_biasPart[8][2][Bn][Hn]; // split-K partials for fusion bias
__device__ float g_bias[2*Bn*Hn];          // [sh|oh][b][n]
__device__ float g_At[Bn*Hn*Ln];           // A transposed: [b][h][j]
__device__ float g_Ct[Bn*Hn*Ln];           // C' transposed (b_corr folded): [b][h][i]
__device__ float g_Sh[Mn*Hn];              // relu subj hidden
__device__ float g_Oh[Mn*Hn];              // relu obj hidden

// ---------------- f32x2 helpers (sm_103a packed FMA) ----------------
__device__ __forceinline__ unsigned long long pk2(float x, float y) {
    unsigned long long r;
    asm("mov.b64 %0,{%1,%2};" : "=l"(r) : "f"(x), "f"(y));
    return r;
}
__device__ __forceinline__ unsigned long long fma2(unsigned long long a,
                                                   unsigned long long b,
                                                   unsigned long long c) {
    unsigned long long d;
    asm("fma.rn.f32x2 %0,%1,%2,%3;" : "=l"(d) : "l"(a), "l"(b), "l"(c));
    return d;
}
__device__ __forceinline__ void upk2(unsigned long long v, float& x, float& y) {
    asm("mov.b64 {%0,%1},%2;" : "=f"(x), "=f"(y) : "l"(v));
}

// ---------------- 1) masked mean pool (l-split x4 inside block) ----------------
__global__ __launch_bounds__(256) void pool_kernel(const float* __restrict__ e,
                                                   const float* __restrict__ mask) {
    int b = blockIdx.x;
    int h0 = blockIdx.y * 64;               // grid.y = 12
    int tid = threadIdx.x;
    int lg = tid >> 6, hh = tid & 63;       // 4 l-groups x 64 h
    __shared__ float msm[Ln];
    __shared__ float part[4][64];
    __shared__ float sinv;
    if (tid < Ln) msm[tid] = mask[b*Ln + tid];
    __syncthreads();
    if (tid == 0) {
        float s = 0.f;
        for (int l = 0; l < Ln; l++) s += msm[l];
        sinv = 1.f / s;
    }
    const float* ep = e + (size_t)b*Ln*Hn + (size_t)(lg*32)*Hn + h0 + hh;
    float acc = 0.f;
    #pragma unroll 8
    for (int l = 0; l < 32; l++) acc += ep[(size_t)l*Hn] * msm[lg*32 + l];
    part[lg][hh] = acc;
    __syncthreads();
    if (tid < 64) {
        float s = part[0][tid] + part[1][tid] + part[2][tid] + part[3][tid];
        g_pool[b*Hn + h0 + tid] = s * sinv;
    }
}

// ---------------- 2a) rel hidden partials: pool@W_hr (split-K x4) ----------------
__global__ __launch_bounds__(128) void relhid_kernel(const float* __restrict__ W_hr) {
    int r  = blockIdx.x * 128 + threadIdx.x;   // grid.x = 3
    int b  = blockIdx.y;
    int k0 = blockIdx.z * 192;                 // grid.z = 4
    __shared__ float ps[192];
    for (int i = threadIdx.x; i < 192; i += 128) ps[i] = g_pool[b*Hn + k0 + i];
    __syncthreads();
    float acc = 0.f;
    #pragma unroll 8
    for (int h = 0; h < 192; h++) acc += ps[h] * W_hr[(size_t)(k0+h)*RH + r];
    g_rhPart[blockIdx.z][b][r] = acc;
}

// ---------------- 2b) stage1 out: relu(reduce)+bias @ W_rj + b_rj ----------------
__global__ __launch_bounds__(RH) void stage2_kernel(const float* __restrict__ b_hr,
                                                    const float* __restrict__ W_rj,
                                                    const float* __restrict__ b_rj,
                                                    float* __restrict__ out) {
    int b = blockIdx.x;
    int tid = threadIdx.x;   // 384
    __shared__ float rs[RH];
    __shared__ float red[16][Rn];
    float v = g_rhPart[0][b][tid] + g_rhPart[1][b][tid]
            + g_rhPart[2][b][tid] + g_rhPart[3][b][tid] + b_hr[tid];
    rs[tid] = fmaxf(v, 0.f);
    __syncthreads();
    int j = tid % Rn, part = tid / Rn;   // 16 parts x 24 j
    float acc = 0.f;
    #pragma unroll
    for (int q = 0; q < 24; q++) {
        int r = part*24 + q;
        acc += rs[r] * W_rj[r*Rn + j];
    }
    red[part][j] = acc;
    __syncthreads();
    if (tid < Rn) {
        float s = b_rj[tid];
        #pragma unroll
        for (int p = 0; p < 16; p++) s += red[p][tid];
        out[b*Rn + tid] = s;
    }
}

// ---------------- 3a) fusion bias partials: re@W_top (split-K x8) ----------------
// grid (6 n-chunks, 8 k-splits, 2 z), 128 threads. Every coalesced W load is
// amortized across all 8 batches.
__global__ __launch_bounds__(128) void bias_part_kernel(const float* __restrict__ rel_emb,
                                                        const int* __restrict__ target,
                                                        const float* __restrict__ W_sh,
                                                        const float* __restrict__ W_oh) {
    int n  = blockIdx.x * 128 + threadIdx.x;   // grid.x = 6
    int ks = blockIdx.y;                       // grid.y = 8
    int z  = blockIdx.z;                       // grid.z = 2
    const float* W = z ? W_oh : W_sh;          // top half rows 0..767
    int k0 = ks * 96;
    __shared__ float re[Bn][96];
    for (int i = threadIdx.x; i < Bn*96; i += 128) {
        int b = i / 96, kk = i % 96;
        re[b][kk] = rel_emb[(size_t)target[b]*Hn + k0 + kk];
    }
    __syncthreads();
    float acc[Bn];
    #pragma unroll
    for (int b = 0; b < Bn; b++) acc[b] = 0.f;
    #pragma unroll 4
    for (int kk = 0; kk < 96; kk++) {
        float w = W[(size_t)(k0+kk)*Hn + n];
        #pragma unroll
        for (int b = 0; b < Bn; b++) acc[b] += re[b][kk] * w;
    }
    #pragma unroll
    for (int b = 0; b < Bn; b++) g_biasPart[ks][z][b][n] = acc[b];
}

// ---------------- 3b) reduce partials + bias ----------------
__global__ __launch_bounds__(256) void bias_reduce_kernel(const float* __restrict__ b_sh,
                                                          const float* __restrict__ b_oh) {
    int idx = blockIdx.x * 256 + threadIdx.x;   // 48 blocks -> 12288
    int z = idx / (Bn*Hn);
    int rem = idx % (Bn*Hn);
    int b = rem / Hn, n = rem % Hn;
    float s = (z ? b_oh : b_sh)[n];
    #pragma unroll
    for (int ks = 0; ks < 8; ks++) s += g_biasPart[ks][z][b][n];
    g_bias[z*Bn*Hn + rem] = s;
}

// ---------------- 4) unified GEMM: embed(1024x768) @ W(768x768) ----------------
// 64(M) x 128(N) block tile, BK=16, 128 threads, 8x8 microtile (f32x2 packed).
// z=0: A  -> g_At transposed; z=1: C -> g_Ct transposed + b_corr
// z=2: Sh -> relu(. + g_bias[0][b]); z=3: Oh -> relu(. + g_bias[1][b])
#define GBM 64
#define GBN 128
#define GBK 16
__global__ __launch_bounds__(128, 3) void gemm_kernel(const float* __restrict__ X,
                                                      const float* __restrict__ W_corr,
                                                      const float* __restrict__ W_sh,
                                                      const float* __restrict__ W_oh,
                                                      const float* __restrict__ b_corr) {
    int z = blockIdx.z;
    const float* W;
    if (z == 0)      W = W_corr;
    else if (z == 1) W = W_corr + Hn*Hn;
    else if (z == 2) W = W_sh  + Hn*Hn;
    else             W = W_oh  + Hn*Hn;

    int m0 = blockIdx.y * GBM;
    int n0 = blockIdx.x * GBN;
    int tid = threadIdx.x;
    int lane = tid & 31, wp = tid >> 5;

    __shared__ float As[2][GBK][GBM];    // 2 x 4KB
    __shared__ float Bs[2][GBK][GBN];    // 2 x 8KB

    int ar = tid & 63, ac = tid >> 6;
    const float* Ap = X + (size_t)(m0 + ar)*Hn + ac*8;
    const float* Bp = W + (size_t)(wp*4)*Hn + n0 + lane*4;

    float4 a0 = *(const float4*)Ap;
    float4 a1 = *(const float4*)(Ap + 4);
    float4 bv0 = *(const float4*)(Bp);
    float4 bv1 = *(const float4*)(Bp + Hn);
    float4 bv2 = *(const float4*)(Bp + 2*Hn);
    float4 bv3 = *(const float4*)(Bp + 3*Hn);

    As[0][ac*8+0][ar] = a0.x; As[0][ac*8+1][ar] = a0.y;
    As[0][ac*8+2][ar] = a0.z; As[0][ac*8+3][ar] = a0.w;
    As[0][ac*8+4][ar] = a1.x; As[0][ac*8+5][ar] = a1.y;
    As[0][ac*8+6][ar] = a1.z; As[0][ac*8+7][ar] = a1.w;
    *(float4*)&Bs[0][wp*4+0][lane*4] = bv0;
    *(float4*)&Bs[0][wp*4+1][lane*4] = bv1;
    *(float4*)&Bs[0][wp*4+2][lane*4] = bv2;
    *(float4*)&Bs[0][wp*4+3][lane*4] = bv3;
    __syncthreads();

    int tx = tid & 15, ty = tid >> 4;   // 16 x 8 thread grid -> 128N x 64M

    unsigned long long acc2[4][8];
    #pragma unroll
    for (int p = 0; p < 4; p++)
        #pragma unroll
        for (int j = 0; j < 8; j++) acc2[p][j] = 0ull;

    const int NT = Hn / GBK;   // 48
    for (int t = 0; t < NT; ++t) {
        int cur = t & 1;
        if (t + 1 < NT) {
            const float* ap2 = Ap + (t+1)*GBK;
            a0 = *(const float4*)ap2;
            a1 = *(const float4*)(ap2 + 4);
            const float* bp2 = Bp + (size_t)(t+1)*GBK*Hn;
            bv0 = *(const float4*)(bp2);
            bv1 = *(const float4*)(bp2 + Hn);
            bv2 = *(const float4*)(bp2 + 2*Hn);
            bv3 = *(const float4*)(bp2 + 3*Hn);
        }
        #pragma unroll
        for (int k = 0; k < GBK; k++) {
            float4 af0 = *(const float4*)&As[cur][k][ty*8];
            float4 af1 = *(const float4*)&As[cur][k][ty*8 + 4];
            float4 bf0 = *(const float4*)&Bs[cur][k][tx*8];
            float4 bf1 = *(const float4*)&Bs[cur][k][tx*8 + 4];
            unsigned long long a01 = pk2(af0.x, af0.y);
            unsigned long long a23 = pk2(af0.z, af0.w);
            unsigned long long a45 = pk2(af1.x, af1.y);
            unsigned long long a67 = pk2(af1.z, af1.w);
            float bb[8] = {bf0.x, bf0.y, bf0.z, bf0.w, bf1.x, bf1.y, bf1.z, bf1.w};
            #pragma unroll
            for (int j = 0; j < 8; j++) {
                unsigned long long bj = pk2(bb[j], bb[j]);
                acc2[0][j] = fma2(a01, bj, acc2[0][j]);
                acc2[1][j] = fma2(a23, bj, acc2[1][j]);
                acc2[2][j] = fma2(a45, bj, acc2[2][j]);
                acc2[3][j] = fma2(a67, bj, acc2[3][j]);
            }
        }
        if (t + 1 < NT) {
            int nxt = cur ^ 1;
            As[nxt][ac*8+0][ar] = a0.x; As[nxt][ac*8+1][ar] = a0.y;
            As[nxt][ac*8+2][ar] = a0.z; As[nxt][ac*8+3][ar] = a0.w;
            As[nxt][ac*8+4][ar] = a1.x; As[nxt][ac*8+5][ar] = a1.y;
            As[nxt][ac*8+6][ar] = a1.z; As[nxt][ac*8+7][ar] = a1.w;
            *(float4*)&Bs[nxt][wp*4+0][lane*4] = bv0;
            *(float4*)&Bs[nxt][wp*4+1][lane*4] = bv1;
            *(float4*)&Bs[nxt][wp*4+2][lane*4] = bv2;
            *(float4*)&Bs[nxt][wp*4+3][lane*4] = bv3;
        }
        __syncthreads();
    }

    float cr[8][8];
    #pragma unroll
    for (int j = 0; j < 8; j++) {
        upk2(acc2[0][j], cr[0][j], cr[1][j]);
        upk2(acc2[1][j], cr[2][j], cr[3][j]);
        upk2(acc2[2][j], cr[4][j], cr[5][j]);
        upk2(acc2[3][j], cr[6][j], cr[7][j]);
    }

    if (z <= 1) {
        int bb2 = m0 >> 7;                // BM=64 never straddles batch
        int l0 = (m0 & 127) + ty*8;
        float* base = (z == 1) ? g_Ct : g_At;
        #pragma unroll
        for (int j = 0; j < 8; j++) {
            int n = n0 + tx*8 + j;
            float bias = (z == 1) ? __ldg(&b_corr[n]) : 0.f;
            float4 v0 = make_float4(cr[0][j]+bias, cr[1][j]+bias, cr[2][j]+bias, cr[3][j]+bias);
            float4 v1 = make_float4(cr[4][j]+bias, cr[5][j]+bias, cr[6][j]+bias, cr[7][j]+bias);
            float* d = base + ((size_t)bb2*Hn + n)*Ln + l0;
            *(float4*)d = v0;
            *(float4*)(d + 4) = v1;
        }
    } else {
        float* outp = (z == 2) ? g_Sh : g_Oh;
        const float* bp = g_bias + (z-2)*Bn*Hn + (m0 >> 7)*Hn + n0 + tx*8;
        float4 b4a = *(const float4*)bp;
        float4 b4b = *(const float4*)(bp + 4);
        #pragma unroll
        for (int i = 0; i < 8; i++) {
            int m = m0 + ty*8 + i;
            float4 v0 = make_float4(fmaxf(cr[i][0] + b4a.x, 0.f),
                                    fmaxf(cr[i][1] + b4a.y, 0.f),
                                    fmaxf(cr[i][2] + b4a.z, 0.f),
                                    fmaxf(cr[i][3] + b4a.w, 0.f));
            float4 v1 = make_float4(fmaxf(cr[i][4] + b4b.x, 0.f),
                                    fmaxf(cr[i][5] + b4b.y, 0.f),
                                    fmaxf(cr[i][6] + b4b.z, 0.f),
                                    fmaxf(cr[i][7] + b4b.w, 0.f));
            float* d = outp + (size_t)m*Hn + n0 + tx*8;
            *(float4*)d = v0;
            *(float4*)(d + 4) = v1;
        }
    }
}

// ---------------- 5) fused pred_corres ----------------
// out[b,i,j] = sum_h relu(A_t[b][h][j] + C_t[b][h][i]) * W_gc[h] + b_gc
#define CH 96
__global__ __launch_bounds__(256) void corres_kernel(const float* __restrict__ W_gc,
                                                     const float* __restrict__ b_gc,
                                                     float* __restrict__ outp) {
    int jt = blockIdx.x, it = blockIdx.y, b = blockIdx.z;
    __shared__ float Asm[CH][32];
    __shared__ float Csm[CH][32];
    __shared__ float Wsm[CH];
    int tid = threadIdx.x;
    int tx = tid & 15, ty = tid >> 4;

    const float* Abase = g_At + (size_t)b*Hn*Ln + jt*32;
    const float* Cbase = g_Ct + (size_t)b*Hn*Ln + it*32;

    float acc00 = 0.f, acc01 = 0.f, acc10 = 0.f, acc11 = 0.f;

    for (int hc = 0; hc < Hn; hc += CH) {
        __syncthreads();
        #pragma unroll
        for (int r = 0; r < 3; r++) {
            int idx = tid + r*256;           // 0..767 float4 slots
            int row = idx >> 3;
            int c4  = (idx & 7) << 2;
            *(float4*)&Asm[row][c4] = *(const float4*)&Abase[(size_t)(hc+row)*Ln + c4];
            *(float4*)&Csm[row][c4] = *(const float4*)&Cbase[(size_t)(hc+row)*Ln + c4];
        }
        if (tid < CH) Wsm[tid] = W_gc[hc + tid];
        __syncthreads();
        #pragma unroll 8
        for (int k = 0; k < CH; k++) {
            float2 a = *(const float2*)&Asm[k][tx*2];
            float2 c = *(const float2*)&Csm[k][ty*2];
            float w = Wsm[k];
            acc00 += fmaxf(a.x + c.x, 0.f) * w;
            acc01 += fmaxf(a.y + c.x, 0.f) * w;
            acc10 += fmaxf(a.x + c.y, 0.f) * w;
            acc11 += fmaxf(a.y + c.y, 0.f) * w;
        }
    }
    float bg = __ldg(b_gc);
    int i0 = it*32 + ty*2, j0 = jt*32 + tx*2;
    float* o = outp + ((size_t)b*Ln + i0)*Ln + j0;
    *(float2*)&o[0]   = make_float2(acc00 + bg, acc01 + bg);
    *(float2*)&o[Ln]  = make_float2(acc10 + bg, acc11 + bg);
}

// ---------------- 6) head projections: hidden(1024x768) @ (768x3) ----------------
__global__ __launch_bounds__(256) void head_kernel(const float* __restrict__ W_st,
                                                   const float* __restrict__ b_st,
                                                   const float* __restrict__ W_ot,
                                                   const float* __restrict__ b_ot,
                                                   float* __restrict__ out) {
    int z = blockIdx.y;  // 0=subj,1=obj
    const float* Hbuf = z ? g_Oh : g_Sh;
    const float* Wp = z ? W_ot : W_st;
    const float* bp = z ? b_ot : b_st;
    int w = threadIdx.x >> 5, lane = threadIdx.x & 31;
    int m = blockIdx.x * 8 + w;   // 0..1023
    float a0 = 0.f, a1 = 0.f, a2 = 0.f;
    const float* hr = Hbuf + (size_t)m*Hn;
    for (int h = lane; h < Hn; h += 32) {
        float v = hr[h];
        a0 += v * __ldg(&Wp[h*3 + 0]);
        a1 += v * __ldg(&Wp[h*3 + 1]);
        a2 += v * __ldg(&Wp[h*3 + 2]);
    }
    #pragma unroll
    for (int off = 16; off; off >>= 1) {
        a0 += __shfl_xor_sync(0xFFFFFFFFu, a0, off);
        a1 += __shfl_xor_sync(0xFFFFFFFFu, a1, off);
        a2 += __shfl_xor_sync(0xFFFFFFFFu, a2, off);
    }
    if (lane == 0) {
        float* o = out + (z ? (Rn*Bn + 3*Mn) : (Rn*Bn)) + m*3;
        o[0] = a0 + bp[0];
        o[1] = a1 + bp[1];
        o[2] = a2 + bp[2];
    }
}

// ---------------- launch ----------------
extern "C" void kernel_launch(void* const* d_in, const int* in_sizes, int n_in,
                              void* d_out, int out_size) {
    const float* embed   = (const float*)d_in[0];
    const float* mask    = (const float*)d_in[1];
    const int*   target  = (const int*)  d_in[2];
    const float* W_hr    = (const float*)d_in[3];
    const float* b_hr    = (const float*)d_in[4];
    const float* W_rj    = (const float*)d_in[5];
    const float* b_rj    = (const float*)d_in[6];
    const float* rel_emb = (const float*)d_in[7];
    const float* W_corr  = (const float*)d_in[8];
    const float* b_corr  = (const float*)d_in[9];
    const float* W_gc    = (const float*)d_in[10];
    const float* b_gc    = (const float*)d_in[11];
    const float* W_sh    = (const float*)d_in[12];
    const float* b_sh    = (const float*)d_in[13];
    const float* W_st    = (const float*)d_in[14];
    const float* b_st    = (const float*)d_in[15];
    const float* W_oh    = (const float*)d_in[16];
    const float* b_oh    = (const float*)d_in[17];
    const float* W_ot    = (const float*)d_in[18];
    const float* b_ot    = (const float*)d_in[19];
    float* out = (float*)d_out;

    // out layout: stage1[192] | subj[3072] | obj[3072] | pred_corres[131072]
    pool_kernel       <<<dim3(Bn, 12), 256>>>(embed, mask);
    bias_part_kernel  <<<dim3(6, 8, 2), 128>>>(rel_emb, target, W_sh, W_oh);
    relhid_kernel     <<<dim3(3, Bn, 4), 128>>>(W_hr);
    bias_reduce_kernel<<<48, 256>>>(b_sh, b_oh);
    stage2_kernel     <<<Bn, RH>>>(b_hr, W_rj, b_rj, out);
    gemm_kernel       <<<dim3(Hn/GBN, Mn/GBM, 4), 128>>>(embed, W_corr, W_sh, W_oh, b_corr);
    corres_kernel     <<<dim3(4, 4, Bn), 256>>>(W_gc, b_gc, out + Rn*Bn + 6*Mn);
    head_kernel       <<<dim3(Mn/8, 2), 256>>>(W_st, b_st, W_ot, b_ot, out);
}

// round 15
// speedup vs baseline: 2.6975x; 1.2888x over previous
#include <cuda_runtime.h>
#include <cuda_bf16.h>
#include <cstdint>

// Shapes
#define Bn 8
#define Ln 128
#define Hn 768
#define Rn 24
#define Mn (Bn*Ln)   // 1024
#define RH 384       // Hn/2

// ---------------- scratch (__device__ globals; no allocation) ----------------
__device__ float g_pool[Bn*Hn];
__device__ float g_rhPart[4][Bn][RH];
__device__ float g_biasPart[8][2][Bn][Hn];
__device__ float g_bias[2*Bn*Hn];
__device__ float g_At[Bn*Hn*Ln];           // A transposed: [b][h][j]
__device__ float g_Ct[Bn*Hn*Ln];           // C' transposed (b_corr folded): [b][h][i]
__device__ float g_Sht[Hn*Mn];             // relu subj hidden, transposed [h][m]
__device__ float g_Oht[Hn*Mn];             // relu obj hidden, transposed [h][m]
__device__ float g_headPart[6][2][Mn*3];
// bf16 split operands (16B aligned for uint4/cp.async access)
__device__ __align__(16) __nv_bfloat16 g_Xhi[Mn*Hn];
__device__ __align__(16) __nv_bfloat16 g_Xlo[Mn*Hn];
__device__ __align__(16) __nv_bfloat16 g_Wthi[4*Hn*Hn];  // [z][n][k]
__device__ __align__(16) __nv_bfloat16 g_Wtlo[4*Hn*Hn];

// ---------------- PTX helpers (sm_80-era: work under compute_103) ----------------
__device__ __forceinline__ uint32_t smem_u32(const void* p) {
    uint32_t a;
    asm("{ .reg .u64 t; cvta.to.shared.u64 t, %1; cvt.u32.u64 %0, t; }" : "=r"(a) : "l"(p));
    return a;
}
__device__ __forceinline__ void ldm4(uint32_t* r, uint32_t addr) {
    asm volatile("ldmatrix.sync.aligned.m8n8.x4.shared.b16 {%0,%1,%2,%3}, [%4];"
        : "=r"(r[0]), "=r"(r[1]), "=r"(r[2]), "=r"(r[3]) : "r"(addr));
}
__device__ __forceinline__ void mma16816(float* c, const uint32_t* a,
                                         uint32_t b0, uint32_t b1) {
    asm volatile("mma.sync.aligned.m16n8k16.row.col.f32.bf16.bf16.f32 "
        "{%0,%1,%2,%3}, {%4,%5,%6,%7}, {%8,%9}, {%0,%1,%2,%3};"
        : "+f"(c[0]), "+f"(c[1]), "+f"(c[2]), "+f"(c[3])
        : "r"(a[0]), "r"(a[1]), "r"(a[2]), "r"(a[3]), "r"(b0), "r"(b1));
}
__device__ __forceinline__ void cp16(uint32_t d, const void* s) {
    asm volatile("cp.async.ca.shared.global [%0], [%1], 16;" :: "r"(d), "l"(s) : "memory");
}
#define CP_COMMIT() asm volatile("cp.async.commit_group;" ::: "memory")
#define CP_WAIT1()  asm volatile("cp.async.wait_group 1;" ::: "memory")
#define CP_WAIT0()  asm volatile("cp.async.wait_group 0;" ::: "memory")

// ---------------- 0a) X -> hi/lo bf16 ----------------
__global__ __launch_bounds__(256) void convX_kernel(const float* __restrict__ e) {
    int i = blockIdx.x * 256 + threadIdx.x;   // grid 768 -> 196608 float4s
    float4 v = ((const float4*)e)[i];
    float xs[4] = {v.x, v.y, v.z, v.w};
    unsigned short hs[4], ls[4];
    #pragma unroll
    for (int k = 0; k < 4; k++) {
        __nv_bfloat16 h = __float2bfloat16(xs[k]);
        float res = xs[k] - __bfloat162float(h);
        __nv_bfloat16 l = __float2bfloat16(res);
        hs[k] = __bfloat16_as_ushort(h);
        ls[k] = __bfloat16_as_ushort(l);
    }
    uint2 wh, wl;
    wh.x = (uint32_t)hs[0] | ((uint32_t)hs[1] << 16);
    wh.y = (uint32_t)hs[2] | ((uint32_t)hs[3] << 16);
    wl.x = (uint32_t)ls[0] | ((uint32_t)ls[1] << 16);
    wl.y = (uint32_t)ls[2] | ((uint32_t)ls[3] << 16);
    *(uint2*)&g_Xhi[(size_t)i*4] = wh;
    *(uint2*)&g_Xlo[(size_t)i*4] = wl;
}

// ---------------- 0b) W -> transposed hi/lo bf16 [z][n][k] ----------------
__global__ __launch_bounds__(256) void convW_kernel(const float* __restrict__ W_corr,
                                                    const float* __restrict__ W_sh,
                                                    const float* __restrict__ W_oh) {
    int z = blockIdx.z;
    const float* Wsrc;
    if (z == 0)      Wsrc = W_corr;
    else if (z == 1) Wsrc = W_corr + Hn*Hn;
    else if (z == 2) Wsrc = W_sh  + Hn*Hn;
    else             Wsrc = W_oh  + Hn*Hn;
    __shared__ float tile[32][33];
    int tx = threadIdx.x & 31, ty = threadIdx.x >> 5;
    int k0 = blockIdx.x * 32, n0 = blockIdx.y * 32;
    #pragma unroll
    for (int r = 0; r < 4; r++) {
        int kk = k0 + ty + r*8;
        tile[ty + r*8][tx] = Wsrc[(size_t)kk*Hn + n0 + tx];
    }
    __syncthreads();
    #pragma unroll
    for (int r = 0; r < 4; r++) {
        int nn = n0 + ty + r*8;
        float v = tile[tx][ty + r*8];
        __nv_bfloat16 h = __float2bfloat16(v);
        float res = v - __bfloat162float(h);
        __nv_bfloat16 l = __float2bfloat16(res);
        size_t idx = (size_t)z*Hn*Hn + (size_t)nn*Hn + k0 + tx;
        g_Wthi[idx] = h;
        g_Wtlo[idx] = l;
    }
}

// ---------------- 1) masked mean pool (l-split x4 inside block) ----------------
__global__ __launch_bounds__(256) void pool_kernel(const float* __restrict__ e,
                                                   const float* __restrict__ mask) {
    int b = blockIdx.x;
    int h0 = blockIdx.y * 64;               // grid.y = 12
    int tid = threadIdx.x;
    int lg = tid >> 6, hh = tid & 63;
    __shared__ float msm[Ln];
    __shared__ float part[4][64];
    __shared__ float sinv;
    if (tid < Ln) msm[tid] = mask[b*Ln + tid];
    __syncthreads();
    if (tid == 0) {
        float s = 0.f;
        for (int l = 0; l < Ln; l++) s += msm[l];
        sinv = 1.f / s;
    }
    const float* ep = e + (size_t)b*Ln*Hn + (size_t)(lg*32)*Hn + h0 + hh;
    float acc = 0.f;
    #pragma unroll 8
    for (int l = 0; l < 32; l++) acc += ep[(size_t)l*Hn] * msm[lg*32 + l];
    part[lg][hh] = acc;
    __syncthreads();
    if (tid < 64) {
        float s = part[0][tid] + part[1][tid] + part[2][tid] + part[3][tid];
        g_pool[b*Hn + h0 + tid] = s * sinv;
    }
}

// ---------------- 2a) rel hidden partials: pool@W_hr (split-K x4) ----------------
__global__ __launch_bounds__(128) void relhid_kernel(const float* __restrict__ W_hr) {
    int r  = blockIdx.x * 128 + threadIdx.x;   // grid.x = 3
    int b  = blockIdx.y;
    int k0 = blockIdx.z * 192;                 // grid.z = 4
    __shared__ float ps[192];
    for (int i = threadIdx.x; i < 192; i += 128) ps[i] = g_pool[b*Hn + k0 + i];
    __syncthreads();
    float acc = 0.f;
    #pragma unroll 8
    for (int h = 0; h < 192; h++) acc += ps[h] * W_hr[(size_t)(k0+h)*RH + r];
    g_rhPart[blockIdx.z][b][r] = acc;
}

// ---------------- 2b) stage1 out ----------------
__global__ __launch_bounds__(RH) void stage2_kernel(const float* __restrict__ b_hr,
                                                    const float* __restrict__ W_rj,
                                                    const float* __restrict__ b_rj,
                                                    float* __restrict__ out) {
    int b = blockIdx.x;
    int tid = threadIdx.x;   // 384
    __shared__ float rs[RH];
    __shared__ float red[16][Rn];
    float v = g_rhPart[0][b][tid] + g_rhPart[1][b][tid]
            + g_rhPart[2][b][tid] + g_rhPart[3][b][tid] + b_hr[tid];
    rs[tid] = fmaxf(v, 0.f);
    __syncthreads();
    int j = tid % Rn, part = tid / Rn;
    float acc = 0.f;
    #pragma unroll
    for (int q = 0; q < 24; q++) {
        int r = part*24 + q;
        acc += rs[r] * W_rj[r*Rn + j];
    }
    red[part][j] = acc;
    __syncthreads();
    if (tid < Rn) {
        float s = b_rj[tid];
        #pragma unroll
        for (int p = 0; p < 16; p++) s += red[p][tid];
        out[b*Rn + tid] = s;
    }
}

// ---------------- 3a) fusion bias partials (split-K x8) ----------------
__global__ __launch_bounds__(128) void bias_part_kernel(const float* __restrict__ rel_emb,
                                                        const int* __restrict__ target,
                                                        const float* __restrict__ W_sh,
                                                        const float* __restrict__ W_oh) {
    int n  = blockIdx.x * 128 + threadIdx.x;
    int ks = blockIdx.y;
    int z  = blockIdx.z;
    const float* W = z ? W_oh : W_sh;
    int k0 = ks * 96;
    __shared__ float re[Bn][96];
    for (int i = threadIdx.x; i < Bn*96; i += 128) {
        int b = i / 96, kk = i % 96;
        re[b][kk] = rel_emb[(size_t)target[b]*Hn + k0 + kk];
    }
    __syncthreads();
    float acc[Bn];
    #pragma unroll
    for (int b = 0; b < Bn; b++) acc[b] = 0.f;
    #pragma unroll 4
    for (int kk = 0; kk < 96; kk++) {
        float w = W[(size_t)(k0+kk)*Hn + n];
        #pragma unroll
        for (int b = 0; b < Bn; b++) acc[b] += re[b][kk] * w;
    }
    #pragma unroll
    for (int b = 0; b < Bn; b++) g_biasPart[ks][z][b][n] = acc[b];
}

// ---------------- 3b) reduce partials + bias ----------------
__global__ __launch_bounds__(256) void bias_reduce_kernel(const float* __restrict__ b_sh,
                                                          const float* __restrict__ b_oh) {
    int idx = blockIdx.x * 256 + threadIdx.x;   // 48 blocks -> 12288
    int z = idx / (Bn*Hn);
    int rem = idx % (Bn*Hn);
    int n = rem % Hn;
    float s = (z ? b_oh : b_sh)[n];
    #pragma unroll
    for (int ks = 0; ks < 8; ks++) s += g_biasPart[ks][z][rem / Hn][n];
    g_bias[z*Bn*Hn + rem] = s;
}

// ---------------- 4) HMMA bf16-split GEMM: X(1024x768) @ W(768x768) x4 ----------------
// CTA tile 128M x 128N, 8 warps (2x4), warp tile 64M x 32N, K chunks of 32,
// cp.async double-buffered. 3 passes: Ahi*Bhi + Ahi*Blo + Alo*Bhi (fp32 acc).
#define KC 32
#define NCH (Hn/KC)        // 24
#define ASTR 40            // bf16 per smem row (32 + 8 pad) -> 80B, conflict-free ldmatrix
#define TILEB (128*ASTR*2) // 10240 bytes per tile
#define BUFB  (4*TILEB)    // 40960 per stage
#define SMEM_MMA (2*BUFB)  // 81920

__global__ __launch_bounds__(256, 2) void mma_gemm_kernel(const float* __restrict__ b_corr) {
    extern __shared__ char smem[];
    uint32_t sb = smem_u32(smem);
    int tid = threadIdx.x, lane = tid & 31, wid = tid >> 5;
    int wx = wid & 3, wy = wid >> 2;       // warp grid 4(N) x 2(M)
    int n0 = blockIdx.x * 128;
    int mt = blockIdx.y;                   // m-tile == batch
    int z  = blockIdx.z;
    int m0 = mt * 128;

    const __nv_bfloat16* Ah = g_Xhi;
    const __nv_bfloat16* Al = g_Xlo;
    const __nv_bfloat16* Bh = g_Wthi + (size_t)z*Hn*Hn;
    const __nv_bfloat16* Bl = g_Wtlo + (size_t)z*Hn*Hn;

    float acc[4][4][4] = {};

    // per-thread fill coordinates: 1024 uint4 per tile, 256 threads x 2 iters
    int fr0 = tid >> 2, fc = tid & 3;      // rows (tid>>2), (tid>>2)+64 ; col 0..3
    // ldmatrix per-lane offsets
    int lrow = lane & 15;
    uint32_t lcol = (uint32_t)((lane >> 4) * 16);  // byte offset: +8 bf16 for hi half

    // fill chunk t into buffer buf
    auto fill = [&](int buf, int t) {
        int k0 = t * KC;
        uint32_t bb = sb + buf * BUFB;
        #pragma unroll
        for (int i = 0; i < 2; i++) {
            int r = fr0 + i*64;
            uint32_t doff = (uint32_t)(r*80 + fc*16);
            size_t ga = (size_t)(m0 + r)*Hn + k0 + fc*8;
            size_t gb = (size_t)(n0 + r)*Hn + k0 + fc*8;
            cp16(bb + 0*TILEB + doff, Ah + ga);
            cp16(bb + 1*TILEB + doff, Al + ga);
            cp16(bb + 2*TILEB + doff, Bh + gb);
            cp16(bb + 3*TILEB + doff, Bl + gb);
        }
    };

    fill(0, 0);
    CP_COMMIT();

    for (int t = 0; t < NCH; t++) {
        if (t + 1 < NCH) {
            fill((t + 1) & 1, t + 1);
            CP_COMMIT();
            CP_WAIT1();
        } else {
            CP_WAIT0();
        }
        __syncthreads();
        uint32_t bb = sb + (t & 1) * BUFB;
        #pragma unroll
        for (int ks = 0; ks < 2; ks++) {
            uint32_t kb = (uint32_t)(ks*32) + lcol;
            uint32_t bh[2][4], bl[2][4];
            #pragma unroll
            for (int fnp = 0; fnp < 2; fnp++) {
                uint32_t nr = (uint32_t)((wx*32 + fnp*16 + lrow) * 80) + kb;
                ldm4(bh[fnp], bb + 2*TILEB + nr);
                ldm4(bl[fnp], bb + 3*TILEB + nr);
            }
            #pragma unroll
            for (int fm = 0; fm < 4; fm++) {
                uint32_t mr = (uint32_t)((wy*64 + fm*16 + lrow) * 80) + kb;
                uint32_t ah[4], al[4];
                ldm4(ah, bb + 0*TILEB + mr);
                ldm4(al, bb + 1*TILEB + mr);
                #pragma unroll
                for (int fn = 0; fn < 4; fn++) {
                    int fnp = fn >> 1, o = fn & 1;
                    mma16816(acc[fm][fn], ah, bh[fnp][o], bh[fnp][o+2]);
                    mma16816(acc[fm][fn], ah, bl[fnp][o], bl[fnp][o+2]);
                    mma16816(acc[fm][fn], al, bh[fnp][o], bh[fnp][o+2]);
                }
            }
        }
        __syncthreads();
    }

    // epilogue: frag (fm,fn): c0=(r,c) c1=(r,c+1) c2=(r+8,c) c3=(r+8,c+1)
    int lr = lane >> 2;
    int lc = (lane & 3) * 2;
    if (z <= 1) {
        float* base = z ? g_Ct : g_At;
        #pragma unroll
        for (int fm = 0; fm < 4; fm++) {
            int ml = wy*64 + fm*16 + lr;
            #pragma unroll
            for (int fn = 0; fn < 4; fn++) {
                int n = n0 + wx*32 + fn*8 + lc;
                float b0 = 0.f, b1 = 0.f;
                if (z == 1) { b0 = __ldg(&b_corr[n]); b1 = __ldg(&b_corr[n+1]); }
                float* p0 = base + ((size_t)mt*Hn + n)*Ln;
                float* p1 = base + ((size_t)mt*Hn + n + 1)*Ln;
                p0[ml]     = acc[fm][fn][0] + b0;
                p1[ml]     = acc[fm][fn][1] + b1;
                p0[ml + 8] = acc[fm][fn][2] + b0;
                p1[ml + 8] = acc[fm][fn][3] + b1;
            }
        }
    } else {
        float* base = (z == 2) ? g_Sht : g_Oht;
        const float* gb = g_bias + (z - 2)*Bn*Hn + mt*Hn;
        #pragma unroll
        for (int fm = 0; fm < 4; fm++) {
            int m = m0 + wy*64 + fm*16 + lr;
            #pragma unroll
            for (int fn = 0; fn < 4; fn++) {
                int n = n0 + wx*32 + fn*8 + lc;
                float b0 = gb[n], b1 = gb[n + 1];
                base[(size_t)n*Mn + m]           = fmaxf(acc[fm][fn][0] + b0, 0.f);
                base[(size_t)(n + 1)*Mn + m]     = fmaxf(acc[fm][fn][1] + b1, 0.f);
                base[(size_t)n*Mn + m + 8]       = fmaxf(acc[fm][fn][2] + b0, 0.f);
                base[(size_t)(n + 1)*Mn + m + 8] = fmaxf(acc[fm][fn][3] + b1, 0.f);
            }
        }
    }
}

// ---------------- 5) fused pred_corres ----------------
// out[b,i,j] = sum_h relu(A_t[b][h][j] + C_t[b][h][i]) * W_gc[h] + b_gc
#define CH 96
__global__ __launch_bounds__(256) void corres_kernel(const float* __restrict__ W_gc,
                                                     const float* __restrict__ b_gc,
                                                     float* __restrict__ outp) {
    int jt = blockIdx.x, it = blockIdx.y, b = blockIdx.z;
    __shared__ float Asm[CH][32];
    __shared__ float Csm[CH][32];
    __shared__ float Wsm[CH];
    int tid = threadIdx.x;
    int tx = tid & 15, ty = tid >> 4;

    const float* Abase = g_At + (size_t)b*Hn*Ln + jt*32;
    const float* Cbase = g_Ct + (size_t)b*Hn*Ln + it*32;

    float acc00 = 0.f, acc01 = 0.f, acc10 = 0.f, acc11 = 0.f;

    for (int hc = 0; hc < Hn; hc += CH) {
        __syncthreads();
        #pragma unroll
        for (int r = 0; r < 3; r++) {
            int idx = tid + r*256;
            int row = idx >> 3;
            int c4  = (idx & 7) << 2;
            *(float4*)&Asm[row][c4] = *(const float4*)&Abase[(size_t)(hc+row)*Ln + c4];
            *(float4*)&Csm[row][c4] = *(const float4*)&Cbase[(size_t)(hc+row)*Ln + c4];
        }
        if (tid < CH) Wsm[tid] = W_gc[hc + tid];
        __syncthreads();
        #pragma unroll 8
        for (int k = 0; k < CH; k++) {
            float2 a = *(const float2*)&Asm[k][tx*2];
            float2 c = *(const float2*)&Csm[k][ty*2];
            float w = Wsm[k];
            acc00 += fmaxf(a.x + c.x, 0.f) * w;
            acc01 += fmaxf(a.y + c.x, 0.f) * w;
            acc10 += fmaxf(a.x + c.y, 0.f) * w;
            acc11 += fmaxf(a.y + c.y, 0.f) * w;
        }
    }
    float bg = __ldg(b_gc);
    int i0 = it*32 + ty*2, j0 = jt*32 + tx*2;
    float* o = outp + ((size_t)b*Ln + i0)*Ln + j0;
    *(float2*)&o[0]   = make_float2(acc00 + bg, acc01 + bg);
    *(float2*)&o[Ln]  = make_float2(acc10 + bg, acc11 + bg);
}

// ---------------- 6a) head partials: Ht[h][m] @ W[h][3] (split-h x6) ----------------
__global__ __launch_bounds__(256) void head_part_kernel(const float* __restrict__ W_st,
                                                        const float* __restrict__ W_ot) {
    int m  = blockIdx.x * 256 + threadIdx.x;   // grid.x = 4
    int hs = blockIdx.y;                       // 6
    int z  = blockIdx.z;                       // 2
    const float* Ht = z ? g_Oht : g_Sht;
    const float* Wp = z ? W_ot : W_st;
    __shared__ float Wsm[128*3];
    for (int i = threadIdx.x; i < 128*3; i += 256) Wsm[i] = Wp[hs*128*3 + i];
    __syncthreads();
    float a0 = 0.f, a1 = 0.f, a2 = 0.f;
    const float* base = Ht + (size_t)hs*128*Mn + m;
    #pragma unroll 4
    for (int h = 0; h < 128; h++) {
        float v = base[(size_t)h*Mn];
        a0 += v * Wsm[h*3 + 0];
        a1 += v * Wsm[h*3 + 1];
        a2 += v * Wsm[h*3 + 2];
    }
    float* o = &g_headPart[hs][z][m*3];
    o[0] = a0; o[1] = a1; o[2] = a2;
}

// ---------------- 6b) head reduce + bias ----------------
__global__ __launch_bounds__(256) void head_reduce_kernel(const float* __restrict__ b_st,
                                                          const float* __restrict__ b_ot,
                                                          float* __restrict__ out) {
    int idx = blockIdx.x * 256 + threadIdx.x;   // 24 blocks -> 6144
    int z = idx / (Mn*3);
    int r = idx % (Mn*3);
    int j = r % 3;
    float s = (z ? b_ot : b_st)[j];
    #pragma unroll
    for (int hs = 0; hs < 6; hs++) s += g_headPart[hs][z][r];
    out[Rn*Bn + z*Mn*3 + r] = s;
}

// ---------------- launch ----------------
extern "C" void kernel_launch(void* const* d_in, const int* in_sizes, int n_in,
                              void* d_out, int out_size) {
    const float* embed   = (const float*)d_in[0];
    const float* mask    = (const float*)d_in[1];
    const int*   target  = (const int*)  d_in[2];
    const float* W_hr    = (const float*)d_in[3];
    const float* b_hr    = (const float*)d_in[4];
    const float* W_rj    = (const float*)d_in[5];
    const float* b_rj    = (const float*)d_in[6];
    const float* rel_emb = (const float*)d_in[7];
    const float* W_corr  = (const float*)d_in[8];
    const float* b_corr  = (const float*)d_in[9];
    const float* W_gc    = (const float*)d_in[10];
    const float* b_gc    = (const float*)d_in[11];
    const float* W_sh    = (const float*)d_in[12];
    const float* b_sh    = (const float*)d_in[13];
    const float* W_st    = (const float*)d_in[14];
    const float* b_st    = (const float*)d_in[15];
    const float* W_oh    = (const float*)d_in[16];
    const float* b_oh    = (const float*)d_in[17];
    const float* W_ot    = (const float*)d_in[18];
    const float* b_ot    = (const float*)d_in[19];
    float* out = (float*)d_out;

    static int smem_set = 0;
    if (!smem_set) {
        cudaFuncSetAttribute(mma_gemm_kernel,
                             cudaFuncAttributeMaxDynamicSharedMemorySize, SMEM_MMA);
        smem_set = 1;
    }

    // out layout: stage1[192] | subj[3072] | obj[3072] | pred_corres[131072]
    convX_kernel      <<<Mn*Hn/1024, 256>>>(embed);
    convW_kernel      <<<dim3(Hn/32, Hn/32, 4), 256>>>(W_corr, W_sh, W_oh);
    pool_kernel       <<<dim3(Bn, 12), 256>>>(embed, mask);
    bias_part_kernel  <<<dim3(6, 8, 2), 128>>>(rel_emb, target, W_sh, W_oh);
    relhid_kernel     <<<dim3(3, Bn, 4), 128>>>(W_hr);
    bias_reduce_kernel<<<48, 256>>>(b_sh, b_oh);
    stage2_kernel     <<<Bn, RH>>>(b_hr, W_rj, b_rj, out);
    mma_gemm_kernel   <<<dim3(Hn/128, Bn, 4), 256, SMEM_MMA>>>(b_corr);
    corres_kernel     <<<dim3(4, 4, Bn), 256>>>(W_gc, b_gc, out + Rn*Bn + 6*Mn);
    head_part_kernel  <<<dim3(4, 6, 2), 256>>>(W_st, W_ot);
    head_reduce_kernel<<<24, 256>>>(b_st, b_ot, out);
}

// round 16
// speedup vs baseline: 2.7012x; 1.0014x over previous
#include <cuda_runtime.h>
#include <cuda_bf16.h>
#include <cstdint>

// Shapes
#define Bn 8
#define Ln 128
#define Hn 768
#define Rn 24
#define Mn (Bn*Ln)   // 1024
#define RH 384       // Hn/2

// ---------------- scratch (__device__ globals; no allocation) ----------------
__device__ float g_pool[Bn*Hn];
__device__ float g_rhPart[4][Bn][RH];
__device__ float g_biasPart[8][2][Bn][Hn];
__device__ float g_bias[2*Bn*Hn];
__device__ float g_At[Bn*Hn*Ln];           // A transposed: [b][h][j]
__device__ float g_Ct[Bn*Hn*Ln];           // C' transposed (b_corr folded): [b][h][i]
__device__ float g_Sht[Hn*Mn];             // relu subj hidden, transposed [h][m]
__device__ float g_Oht[Hn*Mn];             // relu obj hidden, transposed [h][m]
__device__ float g_headPart[6][2][Mn*3];
// bf16 split operands (16B aligned for uint4/cp.async access)
__device__ __align__(16) __nv_bfloat16 g_Xhi[Mn*Hn];
__device__ __align__(16) __nv_bfloat16 g_Xlo[Mn*Hn];
__device__ __align__(16) __nv_bfloat16 g_Wthi[4*Hn*Hn];  // [z][n][k]
__device__ __align__(16) __nv_bfloat16 g_Wtlo[4*Hn*Hn];

// ---------------- PTX helpers (sm_80-era: work under compute_103) ----------------
__device__ __forceinline__ uint32_t smem_u32(const void* p) {
    uint32_t a;
    asm("{ .reg .u64 t; cvta.to.shared.u64 t, %1; cvt.u32.u64 %0, t; }" : "=r"(a) : "l"(p));
    return a;
}
__device__ __forceinline__ void ldm4(uint32_t* r, uint32_t addr) {
    asm volatile("ldmatrix.sync.aligned.m8n8.x4.shared.b16 {%0,%1,%2,%3}, [%4];"
        : "=r"(r[0]), "=r"(r[1]), "=r"(r[2]), "=r"(r[3]) : "r"(addr));
}
__device__ __forceinline__ void mma16816(float* c, const uint32_t* a,
                                         uint32_t b0, uint32_t b1) {
    asm volatile("mma.sync.aligned.m16n8k16.row.col.f32.bf16.bf16.f32 "
        "{%0,%1,%2,%3}, {%4,%5,%6,%7}, {%8,%9}, {%0,%1,%2,%3};"
        : "+f"(c[0]), "+f"(c[1]), "+f"(c[2]), "+f"(c[3])
        : "r"(a[0]), "r"(a[1]), "r"(a[2]), "r"(a[3]), "r"(b0), "r"(b1));
}
__device__ __forceinline__ void cp16(uint32_t d, const void* s) {
    asm volatile("cp.async.ca.shared.global [%0], [%1], 16;" :: "r"(d), "l"(s) : "memory");
}
#define CP_COMMIT() asm volatile("cp.async.commit_group;" ::: "memory")
#define CP_WAIT1()  asm volatile("cp.async.wait_group 1;" ::: "memory")
#define CP_WAIT0()  asm volatile("cp.async.wait_group 0;" ::: "memory")

// ---------------- 0a) X -> hi/lo bf16 ----------------
__global__ __launch_bounds__(256) void convX_kernel(const float* __restrict__ e) {
    int i = blockIdx.x * 256 + threadIdx.x;   // grid 768 -> 196608 float4s
    float4 v = ((const float4*)e)[i];
    float xs[4] = {v.x, v.y, v.z, v.w};
    unsigned short hs[4], ls[4];
    #pragma unroll
    for (int k = 0; k < 4; k++) {
        __nv_bfloat16 h = __float2bfloat16(xs[k]);
        float res = xs[k] - __bfloat162float(h);
        __nv_bfloat16 l = __float2bfloat16(res);
        hs[k] = __bfloat16_as_ushort(h);
        ls[k] = __bfloat16_as_ushort(l);
    }
    uint2 wh, wl;
    wh.x = (uint32_t)hs[0] | ((uint32_t)hs[1] << 16);
    wh.y = (uint32_t)hs[2] | ((uint32_t)hs[3] << 16);
    wl.x = (uint32_t)ls[0] | ((uint32_t)ls[1] << 16);
    wl.y = (uint32_t)ls[2] | ((uint32_t)ls[3] << 16);
    *(uint2*)&g_Xhi[(size_t)i*4] = wh;
    *(uint2*)&g_Xlo[(size_t)i*4] = wl;
}

// ---------------- 0b) W -> transposed hi/lo bf16 [z][n][k] ----------------
__global__ __launch_bounds__(256) void convW_kernel(const float* __restrict__ W_corr,
                                                    const float* __restrict__ W_sh,
                                                    const float* __restrict__ W_oh) {
    int z = blockIdx.z;
    const float* Wsrc;
    if (z == 0)      Wsrc = W_corr;
    else if (z == 1) Wsrc = W_corr + Hn*Hn;
    else if (z == 2) Wsrc = W_sh  + Hn*Hn;
    else             Wsrc = W_oh  + Hn*Hn;
    __shared__ float tile[32][33];
    int tx = threadIdx.x & 31, ty = threadIdx.x >> 5;
    int k0 = blockIdx.x * 32, n0 = blockIdx.y * 32;
    #pragma unroll
    for (int r = 0; r < 4; r++) {
        int kk = k0 + ty + r*8;
        tile[ty + r*8][tx] = Wsrc[(size_t)kk*Hn + n0 + tx];
    }
    __syncthreads();
    #pragma unroll
    for (int r = 0; r < 4; r++) {
        int nn = n0 + ty + r*8;
        float v = tile[tx][ty + r*8];
        __nv_bfloat16 h = __float2bfloat16(v);
        float res = v - __bfloat162float(h);
        __nv_bfloat16 l = __float2bfloat16(res);
        size_t idx = (size_t)z*Hn*Hn + (size_t)nn*Hn + k0 + tx;
        g_Wthi[idx] = h;
        g_Wtlo[idx] = l;
    }
}

// ---------------- 1) masked mean pool (l-split x4 inside block) ----------------
__global__ __launch_bounds__(256) void pool_kernel(const float* __restrict__ e,
                                                   const float* __restrict__ mask) {
    int b = blockIdx.x;
    int h0 = blockIdx.y * 64;               // grid.y = 12
    int tid = threadIdx.x;
    int lg = tid >> 6, hh = tid & 63;
    __shared__ float msm[Ln];
    __shared__ float part[4][64];
    __shared__ float sinv;
    if (tid < Ln) msm[tid] = mask[b*Ln + tid];
    __syncthreads();
    if (tid == 0) {
        float s = 0.f;
        for (int l = 0; l < Ln; l++) s += msm[l];
        sinv = 1.f / s;
    }
    const float* ep = e + (size_t)b*Ln*Hn + (size_t)(lg*32)*Hn + h0 + hh;
    float acc = 0.f;
    #pragma unroll 8
    for (int l = 0; l < 32; l++) acc += ep[(size_t)l*Hn] * msm[lg*32 + l];
    part[lg][hh] = acc;
    __syncthreads();
    if (tid < 64) {
        float s = part[0][tid] + part[1][tid] + part[2][tid] + part[3][tid];
        g_pool[b*Hn + h0 + tid] = s * sinv;
    }
}

// ---------------- 2a) rel hidden partials: pool@W_hr (split-K x4) ----------------
__global__ __launch_bounds__(128) void relhid_kernel(const float* __restrict__ W_hr) {
    int r  = blockIdx.x * 128 + threadIdx.x;   // grid.x = 3
    int b  = blockIdx.y;
    int k0 = blockIdx.z * 192;                 // grid.z = 4
    __shared__ float ps[192];
    for (int i = threadIdx.x; i < 192; i += 128) ps[i] = g_pool[b*Hn + k0 + i];
    __syncthreads();
    float acc = 0.f;
    #pragma unroll 8
    for (int h = 0; h < 192; h++) acc += ps[h] * W_hr[(size_t)(k0+h)*RH + r];
    g_rhPart[blockIdx.z][b][r] = acc;
}

// ---------------- 2b) stage1 out ----------------
__global__ __launch_bounds__(RH) void stage2_kernel(const float* __restrict__ b_hr,
                                                    const float* __restrict__ W_rj,
                                                    const float* __restrict__ b_rj,
                                                    float* __restrict__ out) {
    int b = blockIdx.x;
    int tid = threadIdx.x;   // 384
    __shared__ float rs[RH];
    __shared__ float red[16][Rn];
    float v = g_rhPart[0][b][tid] + g_rhPart[1][b][tid]
            + g_rhPart[2][b][tid] + g_rhPart[3][b][tid] + b_hr[tid];
    rs[tid] = fmaxf(v, 0.f);
    __syncthreads();
    int j = tid % Rn, part = tid / Rn;
    float acc = 0.f;
    #pragma unroll
    for (int q = 0; q < 24; q++) {
        int r = part*24 + q;
        acc += rs[r] * W_rj[r*Rn + j];
    }
    red[part][j] = acc;
    __syncthreads();
    if (tid < Rn) {
        float s = b_rj[tid];
        #pragma unroll
        for (int p = 0; p < 16; p++) s += red[p][tid];
        out[b*Rn + tid] = s;
    }
}

// ---------------- 3a) fusion bias partials (split-K x8) ----------------
__global__ __launch_bounds__(128) void bias_part_kernel(const float* __restrict__ rel_emb,
                                                        const int* __restrict__ target,
                                                        const float* __restrict__ W_sh,
                                                        const float* __restrict__ W_oh) {
    int n  = blockIdx.x * 128 + threadIdx.x;
    int ks = blockIdx.y;
    int z  = blockIdx.z;
    const float* W = z ? W_oh : W_sh;
    int k0 = ks * 96;
    __shared__ float re[Bn][96];
    for (int i = threadIdx.x; i < Bn*96; i += 128) {
        int b = i / 96, kk = i % 96;
        re[b][kk] = rel_emb[(size_t)target[b]*Hn + k0 + kk];
    }
    __syncthreads();
    float acc[Bn];
    #pragma unroll
    for (int b = 0; b < Bn; b++) acc[b] = 0.f;
    #pragma unroll 4
    for (int kk = 0; kk < 96; kk++) {
        float w = W[(size_t)(k0+kk)*Hn + n];
        #pragma unroll
        for (int b = 0; b < Bn; b++) acc[b] += re[b][kk] * w;
    }
    #pragma unroll
    for (int b = 0; b < Bn; b++) g_biasPart[ks][z][b][n] = acc[b];
}

// ---------------- 3b) reduce partials + bias ----------------
__global__ __launch_bounds__(256) void bias_reduce_kernel(const float* __restrict__ b_sh,
                                                          const float* __restrict__ b_oh) {
    int idx = blockIdx.x * 256 + threadIdx.x;   // 48 blocks -> 12288
    int z = idx / (Bn*Hn);
    int rem = idx % (Bn*Hn);
    int n = rem % Hn;
    float s = (z ? b_oh : b_sh)[n];
    #pragma unroll
    for (int ks = 0; ks < 8; ks++) s += g_biasPart[ks][z][rem / Hn][n];
    g_bias[z*Bn*Hn + rem] = s;
}

// ---------------- 4) HMMA bf16-split GEMM: X(1024x768) @ W(768x768) x4 ----------------
// CTA tile 128M x 128N, 8 warps (2x4), warp tile 64M x 32N, K chunks of 32,
// cp.async double-buffered. 3 passes: Ahi*Bhi + Ahi*Blo + Alo*Bhi (fp32 acc).
#define KC 32
#define NCH (Hn/KC)        // 24
#define ASTR 40            // bf16 per smem row (32 + 8 pad) -> 80B, conflict-free ldmatrix
#define TILEB (128*ASTR*2) // 10240 bytes per tile
#define BUFB  (4*TILEB)    // 40960 per stage
#define SMEM_MMA (2*BUFB)  // 81920

__global__ __launch_bounds__(256, 2) void mma_gemm_kernel(const float* __restrict__ b_corr) {
    extern __shared__ char smem[];
    uint32_t sb = smem_u32(smem);
    int tid = threadIdx.x, lane = tid & 31, wid = tid >> 5;
    int wx = wid & 3, wy = wid >> 2;       // warp grid 4(N) x 2(M)
    int n0 = blockIdx.x * 128;
    int mt = blockIdx.y;                   // m-tile == batch
    int z  = blockIdx.z;
    int m0 = mt * 128;

    const __nv_bfloat16* Ah = g_Xhi;
    const __nv_bfloat16* Al = g_Xlo;
    const __nv_bfloat16* Bh = g_Wthi + (size_t)z*Hn*Hn;
    const __nv_bfloat16* Bl = g_Wtlo + (size_t)z*Hn*Hn;

    float acc[4][4][4] = {};

    // per-thread fill coordinates: 1024 uint4 per tile, 256 threads x 2 iters
    int fr0 = tid >> 2, fc = tid & 3;      // rows (tid>>2), (tid>>2)+64 ; col 0..3
    // ldmatrix per-lane offsets
    int lrow = lane & 15;
    uint32_t lcol = (uint32_t)((lane >> 4) * 16);  // byte offset: +8 bf16 for hi half

    // fill chunk t into buffer buf
    auto fill = [&](int buf, int t) {
        int k0 = t * KC;
        uint32_t bb = sb + buf * BUFB;
        #pragma unroll
        for (int i = 0; i < 2; i++) {
            int r = fr0 + i*64;
            uint32_t doff = (uint32_t)(r*80 + fc*16);
            size_t ga = (size_t)(m0 + r)*Hn + k0 + fc*8;
            size_t gb = (size_t)(n0 + r)*Hn + k0 + fc*8;
            cp16(bb + 0*TILEB + doff, Ah + ga);
            cp16(bb + 1*TILEB + doff, Al + ga);
            cp16(bb + 2*TILEB + doff, Bh + gb);
            cp16(bb + 3*TILEB + doff, Bl + gb);
        }
    };

    fill(0, 0);
    CP_COMMIT();

    for (int t = 0; t < NCH; t++) {
        if (t + 1 < NCH) {
            fill((t + 1) & 1, t + 1);
            CP_COMMIT();
            CP_WAIT1();
        } else {
            CP_WAIT0();
        }
        __syncthreads();
        uint32_t bb = sb + (t & 1) * BUFB;
        #pragma unroll
        for (int ks = 0; ks < 2; ks++) {
            uint32_t kb = (uint32_t)(ks*32) + lcol;
            uint32_t bh[2][4], bl[2][4];
            #pragma unroll
            for (int fnp = 0; fnp < 2; fnp++) {
                uint32_t nr = (uint32_t)((wx*32 + fnp*16 + lrow) * 80) + kb;
                ldm4(bh[fnp], bb + 2*TILEB + nr);
                ldm4(bl[fnp], bb + 3*TILEB + nr);
            }
            #pragma unroll
            for (int fm = 0; fm < 4; fm++) {
                uint32_t mr = (uint32_t)((wy*64 + fm*16 + lrow) * 80) + kb;
                uint32_t ah[4], al[4];
                ldm4(ah, bb + 0*TILEB + mr);
                ldm4(al, bb + 1*TILEB + mr);
                #pragma unroll
                for (int fn = 0; fn < 4; fn++) {
                    int fnp = fn >> 1, o = fn & 1;
                    mma16816(acc[fm][fn], ah, bh[fnp][o], bh[fnp][o+2]);
                    mma16816(acc[fm][fn], ah, bl[fnp][o], bl[fnp][o+2]);
                    mma16816(acc[fm][fn], al, bh[fnp][o], bh[fnp][o+2]);
                }
            }
        }
        __syncthreads();
    }

    // epilogue: frag (fm,fn): c0=(r,c) c1=(r,c+1) c2=(r+8,c) c3=(r+8,c+1)
    int lr = lane >> 2;
    int lc = (lane & 3) * 2;
    if (z <= 1) {
        float* base = z ? g_Ct : g_At;
        #pragma unroll
        for (int fm = 0; fm < 4; fm++) {
            int ml = wy*64 + fm*16 + lr;
            #pragma unroll
            for (int fn = 0; fn < 4; fn++) {
                int n = n0 + wx*32 + fn*8 + lc;
                float b0 = 0.f, b1 = 0.f;
                if (z == 1) { b0 = __ldg(&b_corr[n]); b1 = __ldg(&b_corr[n+1]); }
                float* p0 = base + ((size_t)mt*Hn + n)*Ln;
                float* p1 = base + ((size_t)mt*Hn + n + 1)*Ln;
                p0[ml]     = acc[fm][fn][0] + b0;
                p1[ml]     = acc[fm][fn][1] + b1;
                p0[ml + 8] = acc[fm][fn][2] + b0;
                p1[ml + 8] = acc[fm][fn][3] + b1;
            }
        }
    } else {
        float* base = (z == 2) ? g_Sht : g_Oht;
        const float* gb = g_bias + (z - 2)*Bn*Hn + mt*Hn;
        #pragma unroll
        for (int fm = 0; fm < 4; fm++) {
            int m = m0 + wy*64 + fm*16 + lr;
            #pragma unroll
            for (int fn = 0; fn < 4; fn++) {
                int n = n0 + wx*32 + fn*8 + lc;
                float b0 = gb[n], b1 = gb[n + 1];
                base[(size_t)n*Mn + m]           = fmaxf(acc[fm][fn][0] + b0, 0.f);
                base[(size_t)(n + 1)*Mn + m]     = fmaxf(acc[fm][fn][1] + b1, 0.f);
                base[(size_t)n*Mn + m + 8]       = fmaxf(acc[fm][fn][2] + b0, 0.f);
                base[(size_t)(n + 1)*Mn + m + 8] = fmaxf(acc[fm][fn][3] + b1, 0.f);
            }
        }
    }
}

// ---------------- 5) fused pred_corres ----------------
// out[b,i,j] = sum_h relu(A_t[b][h][j] + C_t[b][h][i]) * W_gc[h] + b_gc
#define CH 96
__global__ __launch_bounds__(256) void corres_kernel(const float* __restrict__ W_gc,
                                                     const float* __restrict__ b_gc,
                                                     float* __restrict__ outp) {
    int jt = blockIdx.x, it = blockIdx.y, b = blockIdx.z;
    __shared__ float Asm[CH][32];
    __shared__ float Csm[CH][32];
    __shared__ float Wsm[CH];
    int tid = threadIdx.x;
    int tx = tid & 15, ty = tid >> 4;

    const float* Abase = g_At + (size_t)b*Hn*Ln + jt*32;
    const float* Cbase = g_Ct + (size_t)b*Hn*Ln + it*32;

    float acc00 = 0.f, acc01 = 0.f, acc10 = 0.f, acc11 = 0.f;

    for (int hc = 0; hc < Hn; hc += CH) {
        __syncthreads();
        #pragma unroll
        for (int r = 0; r < 3; r++) {
            int idx = tid + r*256;
            int row = idx >> 3;
            int c4  = (idx & 7) << 2;
            *(float4*)&Asm[row][c4] = *(const float4*)&Abase[(size_t)(hc+row)*Ln + c4];
            *(float4*)&Csm[row][c4] = *(const float4*)&Cbase[(size_t)(hc+row)*Ln + c4];
        }
        if (tid < CH) Wsm[tid] = W_gc[hc + tid];
        __syncthreads();
        #pragma unroll 8
        for (int k = 0; k < CH; k++) {
            float2 a = *(const float2*)&Asm[k][tx*2];
            float2 c = *(const float2*)&Csm[k][ty*2];
            float w = Wsm[k];
            acc00 += fmaxf(a.x + c.x, 0.f) * w;
            acc01 += fmaxf(a.y + c.x, 0.f) * w;
            acc10 += fmaxf(a.x + c.y, 0.f) * w;
            acc11 += fmaxf(a.y + c.y, 0.f) * w;
        }
    }
    float bg = __ldg(b_gc);
    int i0 = it*32 + ty*2, j0 = jt*32 + tx*2;
    float* o = outp + ((size_t)b*Ln + i0)*Ln + j0;
    *(float2*)&o[0]   = make_float2(acc00 + bg, acc01 + bg);
    *(float2*)&o[Ln]  = make_float2(acc10 + bg, acc11 + bg);
}

// ---------------- 6a) head partials: Ht[h][m] @ W[h][3] (split-h x6) ----------------
__global__ __launch_bounds__(256) void head_part_kernel(const float* __restrict__ W_st,
                                                        const float* __restrict__ W_ot) {
    int m  = blockIdx.x * 256 + threadIdx.x;   // grid.x = 4
    int hs = blockIdx.y;                       // 6
    int z  = blockIdx.z;                       // 2
    const float* Ht = z ? g_Oht : g_Sht;
    const float* Wp = z ? W_ot : W_st;
    __shared__ float Wsm[128*3];
    for (int i = threadIdx.x; i < 128*3; i += 256) Wsm[i] = Wp[hs*128*3 + i];
    __syncthreads();
    float a0 = 0.f, a1 = 0.f, a2 = 0.f;
    const float* base = Ht + (size_t)hs*128*Mn + m;
    #pragma unroll 4
    for (int h = 0; h < 128; h++) {
        float v = base[(size_t)h*Mn];
        a0 += v * Wsm[h*3 + 0];
        a1 += v * Wsm[h*3 + 1];
        a2 += v * Wsm[h*3 + 2];
    }
    float* o = &g_headPart[hs][z][m*3];
    o[0] = a0; o[1] = a1; o[2] = a2;
}

// ---------------- 6b) head reduce + bias ----------------
__global__ __launch_bounds__(256) void head_reduce_kernel(const float* __restrict__ b_st,
                                                          const float* __restrict__ b_ot,
                                                          float* __restrict__ out) {
    int idx = blockIdx.x * 256 + threadIdx.x;   // 24 blocks -> 6144
    int z = idx / (Mn*3);
    int r = idx % (Mn*3);
    int j = r % 3;
    float s = (z ? b_ot : b_st)[j];
    #pragma unroll
    for (int hs = 0; hs < 6; hs++) s += g_headPart[hs][z][r];
    out[Rn*Bn + z*Mn*3 + r] = s;
}

// ---------------- launch ----------------
extern "C" void kernel_launch(void* const* d_in, const int* in_sizes, int n_in,
                              void* d_out, int out_size) {
    const float* embed   = (const float*)d_in[0];
    const float* mask    = (const float*)d_in[1];
    const int*   target  = (const int*)  d_in[2];
    const float* W_hr    = (const float*)d_in[3];
    const float* b_hr    = (const float*)d_in[4];
    const float* W_rj    = (const float*)d_in[5];
    const float* b_rj    = (const float*)d_in[6];
    const float* rel_emb = (const float*)d_in[7];
    const float* W_corr  = (const float*)d_in[8];
    const float* b_corr  = (const float*)d_in[9];
    const float* W_gc    = (const float*)d_in[10];
    const float* b_gc    = (const float*)d_in[11];
    const float* W_sh    = (const float*)d_in[12];
    const float* b_sh    = (const float*)d_in[13];
    const float* W_st    = (const float*)d_in[14];
    const float* b_st    = (const float*)d_in[15];
    const float* W_oh    = (const float*)d_in[16];
    const float* b_oh    = (const float*)d_in[17];
    const float* W_ot    = (const float*)d_in[18];
    const float* b_ot    = (const float*)d_in[19];
    float* out = (float*)d_out;

    static int smem_set = 0;
    if (!smem_set) {
        cudaFuncSetAttribute(mma_gemm_kernel,
                             cudaFuncAttributeMaxDynamicSharedMemorySize, SMEM_MMA);
        smem_set = 1;
    }

    // out layout: stage1[192] | subj[3072] | obj[3072] | pred_corres[131072]
    convX_kernel      <<<Mn*Hn/1024, 256>>>(embed);
    convW_kernel      <<<dim3(Hn/32, Hn/32, 4), 256>>>(W_corr, W_sh, W_oh);
    pool_kernel       <<<dim3(Bn, 12), 256>>>(embed, mask);
    bias_part_kernel  <<<dim3(6, 8, 2), 128>>>(rel_emb, target, W_sh, W_oh);
    relhid_kernel     <<<dim3(3, Bn, 4), 128>>>(W_hr);
    bias_reduce_kernel<<<48, 256>>>(b_sh, b_oh);
    stage2_kernel     <<<Bn, RH>>>(b_hr, W_rj, b_rj, out);
    mma_gemm_kernel   <<<dim3(Hn/128, Bn, 4), 256, SMEM_MMA>>>(b_corr);
    corres_kernel     <<<dim3(4, 4, Bn), 256>>>(W_gc, b_gc, out + Rn*Bn + 6*Mn);
    head_part_kernel  <<<dim3(4, 6, 2), 256>>>(W_st, W_ot);
    head_reduce_kernel<<<24, 256>>>(b_st, b_ot, out);
}